// round 1
// baseline (speedup 1.0000x reference)
#include <cuda_runtime.h>

#define B_ 8
#define L_ 1030
#define D_ 1024
#define H_ 16
#define M_ (B_*L_)          // 8240

static const size_t OUT_ELEMS  = (size_t)M_ * D_;              // 8,437,760
static const size_t ATTN_ELEMS = (size_t)B_ * H_ * L_ * L_;    // 135,795,200

// Scratch (device globals: no runtime allocation allowed)
__device__ float g_xn[M_*D_];
__device__ float g_q [M_*D_];
__device__ float g_k [M_*D_];
__device__ float g_v [M_*D_];
__device__ float g_ao[M_*D_];

// ---------------------------------------------------------------- LayerNorm
__global__ void __launch_bounds__(256) ln_kernel(const float* __restrict__ x,
                                                 const float* __restrict__ gam,
                                                 const float* __restrict__ bet)
{
    int row = blockIdx.x;
    int t = threadIdx.x;
    const float4* xr = reinterpret_cast<const float4*>(x + (size_t)row * D_);
    float4 v = xr[t];
    float s  = v.x + v.y + v.z + v.w;
    float ss = v.x*v.x + v.y*v.y + v.z*v.z + v.w*v.w;
    __shared__ float rs[8], rss[8], stat[2];
    #pragma unroll
    for (int o = 16; o; o >>= 1) {
        s  += __shfl_xor_sync(0xffffffffu, s,  o);
        ss += __shfl_xor_sync(0xffffffffu, ss, o);
    }
    if ((t & 31) == 0) { rs[t >> 5] = s; rss[t >> 5] = ss; }
    __syncthreads();
    if (t == 0) {
        float S = 0.f, SS = 0.f;
        #pragma unroll
        for (int i = 0; i < 8; i++) { S += rs[i]; SS += rss[i]; }
        float mu  = S / (float)D_;
        float var = SS / (float)D_ - mu * mu;
        stat[0] = mu;
        stat[1] = rsqrtf(var + 1e-6f);
    }
    __syncthreads();
    float mu = stat[0], inv = stat[1];
    float4 g4 = reinterpret_cast<const float4*>(gam)[t];
    float4 b4 = reinterpret_cast<const float4*>(bet)[t];
    float4 o;
    o.x = (v.x - mu) * inv * g4.x + b4.x;
    o.y = (v.y - mu) * inv * g4.y + b4.y;
    o.z = (v.z - mu) * inv * g4.z + b4.z;
    o.w = (v.w - mu) * inv * g4.w + b4.w;
    reinterpret_cast<float4*>(g_xn + (size_t)row * D_)[t] = o;
}

// ---------------------------------------------------------------- SGEMM 128x128x8
// C[M,1024] = A[M,1024] * W[1024,1024]  (+ bias + resid)
__global__ void __launch_bounds__(256) sgemm_nn(const float* __restrict__ A,
                                                const float* __restrict__ W,
                                                float* __restrict__ C, int M,
                                                const float* __restrict__ bias,
                                                const float* __restrict__ resid)
{
    __shared__ float As[8][128];
    __shared__ float Bs[8][128];
    const int tid = threadIdx.x;
    const int tx = tid & 15, ty = tid >> 4;
    const int bx = blockIdx.x, by = blockIdx.y;
    const int ar = tid >> 1, ac = (tid & 1) << 2;
    const int br = tid >> 5, bc = (tid & 31) << 2;
    const int rowBase = by * 128;

    float acc[8][8];
    #pragma unroll
    for (int i = 0; i < 8; i++)
        #pragma unroll
        for (int j = 0; j < 8; j++) acc[i][j] = 0.f;

    for (int kt = 0; kt < 1024; kt += 8) {
        float4 av = make_float4(0.f, 0.f, 0.f, 0.f);
        if (rowBase + ar < M)
            av = *reinterpret_cast<const float4*>(A + (size_t)(rowBase + ar) * 1024 + kt + ac);
        float4 bv = *reinterpret_cast<const float4*>(W + (size_t)(kt + br) * 1024 + bx * 128 + bc);
        __syncthreads();
        As[ac + 0][ar] = av.x; As[ac + 1][ar] = av.y;
        As[ac + 2][ar] = av.z; As[ac + 3][ar] = av.w;
        *reinterpret_cast<float4*>(&Bs[br][bc]) = bv;
        __syncthreads();
        #pragma unroll
        for (int kk = 0; kk < 8; kk++) {
            float a[8], bb[8];
            #pragma unroll
            for (int i = 0; i < 8; i++) a[i]  = As[kk][ty * 8 + i];
            #pragma unroll
            for (int j = 0; j < 8; j++) bb[j] = Bs[kk][tx * 8 + j];
            #pragma unroll
            for (int i = 0; i < 8; i++)
                #pragma unroll
                for (int j = 0; j < 8; j++) acc[i][j] += a[i] * bb[j];
        }
    }

    #pragma unroll
    for (int i = 0; i < 8; i++) {
        int row = rowBase + ty * 8 + i;
        if (row >= M) continue;
        int col = bx * 128 + tx * 8;
        size_t base = (size_t)row * 1024 + col;
        #pragma unroll
        for (int j = 0; j < 8; j++) {
            float val = acc[i][j];
            if (bias)  val += bias[col + j];
            if (resid) val += resid[base + j];
            C[base + j] = val;
        }
    }
}

// ---------------------------------------------------------------- segment fix-up
// Rows l in [1027,1030) of each batch must use weight set 1. Recompute them.
__global__ void __launch_bounds__(256) seg_fix(const float* __restrict__ wq1,
                                               const float* __restrict__ wk1,
                                               const float* __restrict__ wv1)
{
    int which = blockIdx.y;
    const float* W = (which == 0) ? wq1 : (which == 1) ? wk1 : wv1;
    float* O       = (which == 0) ? g_q : (which == 1) ? g_k : g_v;
    int batch = blockIdx.x / 3, s = blockIdx.x % 3;
    int row = batch * L_ + (L_ - 3) + s;

    __shared__ float xs[1024];
    for (int i = threadIdx.x; i < 1024; i += 256) xs[i] = g_xn[(size_t)row * 1024 + i];
    __syncthreads();

    float a0 = 0.f, a1 = 0.f, a2 = 0.f, a3 = 0.f;
    const float* Wc = W + threadIdx.x;
    for (int k = 0; k < 1024; k++) {
        float xv = xs[k];
        const float* wr = Wc + (size_t)k * 1024;
        a0 += xv * wr[0];
        a1 += xv * wr[256];
        a2 += xv * wr[512];
        a3 += xv * wr[768];
    }
    float* o = O + (size_t)row * 1024 + threadIdx.x;
    o[0] = a0; o[256] = a1; o[512] = a2; o[768] = a3;
}

// ---------------------------------------------------------------- fused attention
// One block per (b, h, 32-query tile). Full score rows in smem.
#define S_STRIDE 1032
#define KSTR 65
#define VSTR 66

__global__ void __launch_bounds__(256) attn_kernel(float* __restrict__ attn_out)
{
    extern __shared__ float sm[];
    float* S  = sm;                       // 32 x 1032
    float* Ks = sm + 32 * S_STRIDE;       // 128 x 66 (stride 65 for K, 66 for V)
    float* Qs = Ks + 128 * VSTR;          // 32 x 64

    const int tid = threadIdx.x;
    const int qt = blockIdx.x, h = blockIdx.y, b = blockIdx.z;
    const int q0 = qt * 32;
    const size_t headq = (size_t)b * L_ * 1024 + h * 64;  // + l*1024 + d

    // load Q tile (pre-scaled by 1/sqrt(dk) = 0.125)
    for (int idx = tid; idx < 32 * 64; idx += 256) {
        int r = idx >> 6, d = idx & 63;
        int l = q0 + r;
        Qs[idx] = (l < L_) ? g_q[headq + (size_t)l * 1024 + d] * 0.125f : 0.f;
    }

    const int tx = tid & 31, ty = tid >> 5;

    // ---- scores: S[q][j] = Q.K^T ----
    for (int kt = 0; kt < L_; kt += 128) {
        __syncthreads();
        for (int idx = tid; idx < 128 * 64; idx += 256) {
            int r = idx >> 6, d = idx & 63;
            int l = kt + r;
            Ks[r * KSTR + d] = (l < L_) ? g_k[headq + (size_t)l * 1024 + d] : 0.f;
        }
        __syncthreads();
        float acc[4][4];
        #pragma unroll
        for (int i = 0; i < 4; i++)
            #pragma unroll
            for (int j = 0; j < 4; j++) acc[i][j] = 0.f;
        #pragma unroll 16
        for (int k = 0; k < 64; k++) {
            float aq[4], bk[4];
            #pragma unroll
            for (int i = 0; i < 4; i++) aq[i] = Qs[(ty + 8 * i) * 64 + k];
            #pragma unroll
            for (int j = 0; j < 4; j++) bk[j] = Ks[(tx + 32 * j) * KSTR + k];
            #pragma unroll
            for (int i = 0; i < 4; i++)
                #pragma unroll
                for (int j = 0; j < 4; j++) acc[i][j] += aq[i] * bk[j];
        }
        #pragma unroll
        for (int i = 0; i < 4; i++)
            #pragma unroll
            for (int j = 0; j < 4; j++) {
                int jj = kt + tx + 32 * j;
                if (jj < L_) S[(ty + 8 * i) * S_STRIDE + jj] = acc[i][j];
            }
    }
    __syncthreads();

    // ---- softmax (warp w handles rows 4w..4w+3) + write attn ----
    const int warp = tid >> 5, lane = tid & 31;
    for (int r = warp * 4; r < warp * 4 + 4; r++) {
        int l = q0 + r;
        if (l >= L_) continue;
        float* Sr = S + r * S_STRIDE;
        float m = -1e30f;
        for (int j = lane; j < L_; j += 32) m = fmaxf(m, Sr[j]);
        #pragma unroll
        for (int o = 16; o; o >>= 1) m = fmaxf(m, __shfl_xor_sync(0xffffffffu, m, o));
        float ssum = 0.f;
        for (int j = lane; j < L_; j += 32) { float e = __expf(Sr[j] - m); Sr[j] = e; ssum += e; }
        #pragma unroll
        for (int o = 16; o; o >>= 1) ssum += __shfl_xor_sync(0xffffffffu, ssum, o);
        float inv = 1.f / ssum;
        size_t abase = ((size_t)(b * H_ + h) * L_ + l) * L_;
        for (int j = lane; j < L_; j += 32) {
            float p = Sr[j] * inv;
            Sr[j] = p;
            if (attn_out) attn_out[abase + j] = p;
        }
    }
    __syncthreads();

    // ---- PV: O[q][d] = P . V  (thread: 4 queries x 2 dims via float2) ----
    float o_[4][2];
    #pragma unroll
    for (int i = 0; i < 4; i++) { o_[i][0] = 0.f; o_[i][1] = 0.f; }
    for (int kt = 0; kt < L_; kt += 128) {
        __syncthreads();
        for (int idx = tid; idx < 128 * 64; idx += 256) {
            int r = idx >> 6, d = idx & 63;
            int l = kt + r;
            Ks[r * VSTR + d] = (l < L_) ? g_v[headq + (size_t)l * 1024 + d] : 0.f;
        }
        __syncthreads();
        int lim = (L_ - kt < 128) ? (L_ - kt) : 128;
        for (int j = 0; j < lim; j++) {
            float p[4];
            #pragma unroll
            for (int i = 0; i < 4; i++) p[i] = S[(ty + 8 * i) * S_STRIDE + kt + j];
            float2 v2 = *reinterpret_cast<const float2*>(&Ks[j * VSTR + 2 * tx]);
            #pragma unroll
            for (int i = 0; i < 4; i++) { o_[i][0] += p[i] * v2.x; o_[i][1] += p[i] * v2.y; }
        }
    }
    #pragma unroll
    for (int i = 0; i < 4; i++) {
        int l = q0 + ty + 8 * i;
        if (l < L_) {
            float2 w2; w2.x = o_[i][0]; w2.y = o_[i][1];
            *reinterpret_cast<float2*>(&g_ao[headq + (size_t)l * 1024 + 2 * tx]) = w2;
        }
    }
}

// ---------------------------------------------------------------- launch
extern "C" void kernel_launch(void* const* d_in, const int* in_sizes, int n_in,
                              void* d_out, int out_size)
{
    const float* x    = (const float*)d_in[0];
    const float* wq0  = (const float*)d_in[1];
    const float* wq1  = (const float*)d_in[2];
    const float* wk0  = (const float*)d_in[3];
    const float* wk1  = (const float*)d_in[4];
    const float* wv0  = (const float*)d_in[5];
    const float* wv1  = (const float*)d_in[6];
    const float* fc_w = (const float*)d_in[7];
    const float* fc_b = (const float*)d_in[8];
    const float* ln_g = (const float*)d_in[9];
    const float* ln_b = (const float*)d_in[10];
    float* out = (float*)d_out;

    float *p_xn, *p_q, *p_k, *p_v, *p_ao;
    cudaGetSymbolAddress((void**)&p_xn, g_xn);
    cudaGetSymbolAddress((void**)&p_q,  g_q);
    cudaGetSymbolAddress((void**)&p_k,  g_k);
    cudaGetSymbolAddress((void**)&p_v,  g_v);
    cudaGetSymbolAddress((void**)&p_ao, g_ao);

    float* attn_ptr = ((size_t)out_size >= OUT_ELEMS + ATTN_ELEMS)
                        ? (out + OUT_ELEMS) : nullptr;

    // 1) LayerNorm
    ln_kernel<<<M_, 256>>>(x, ln_g, ln_b);

    // 2) Q/K/V projections (weight set 0 everywhere)
    dim3 gg(8, (M_ + 127) / 128);
    sgemm_nn<<<gg, 256>>>(p_xn, wq0, p_q, M_, nullptr, nullptr);
    sgemm_nn<<<gg, 256>>>(p_xn, wk0, p_k, M_, nullptr, nullptr);
    sgemm_nn<<<gg, 256>>>(p_xn, wv0, p_v, M_, nullptr, nullptr);

    // 3) fix the 24 rows that use weight set 1
    seg_fix<<<dim3(24, 3), 256>>>(wq1, wk1, wv1);

    // 4) fused attention (+ attn output)
    size_t smem = (size_t)(32 * S_STRIDE + 128 * VSTR + 32 * 64) * sizeof(float);
    cudaFuncSetAttribute(attn_kernel, cudaFuncAttributeMaxDynamicSharedMemorySize, (int)smem);
    attn_kernel<<<dim3((L_ + 31) / 32, H_, B_), 256, smem>>>(attn_ptr);

    // 5) FC + bias + residual -> out
    sgemm_nn<<<gg, 256>>>(p_ao, fc_w, out, M_, fc_b, x);
}

// round 5
// speedup vs baseline: 2.3286x; 2.3286x over previous
#include <cuda_runtime.h>
#include <cuda_bf16.h>
#include <cstdint>

#define B_ 8
#define L_ 1030
#define D_ 1024
#define H_ 16
#define M_ (B_*L_)          // 8240

static const size_t OUT_ELEMS  = (size_t)M_ * D_;              // 8,437,760
static const size_t ATTN_ELEMS = (size_t)B_ * H_ * L_ * L_;    // 135,795,200

// Scratch (device globals: no runtime allocation allowed)
__device__ float g_xn[M_*D_];
__device__ float g_q [M_*D_];
__device__ float g_k [M_*D_];
__device__ float g_v [M_*D_];
__device__ float g_ao[M_*D_];
// bf16 split buffers (activations: reused for xn then ao)
__device__ __nv_bfloat16 g_sh[M_*D_];
__device__ __nv_bfloat16 g_sl[M_*D_];
// transposed+split weights: [4][1024*1024]  (wq0, wk0, wv0, fc_w) as [N][K]
__device__ __nv_bfloat16 g_wth[4*1024*1024];
__device__ __nv_bfloat16 g_wtl[4*1024*1024];

// =======================================================================
// helpers
// =======================================================================
static __device__ __forceinline__ uint32_t smem_u32(const void* p) {
    uint32_t a;
    asm("{ .reg .u64 t; cvta.to.shared.u64 t, %1; cvt.u32.u64 %0, t; }"
        : "=r"(a) : "l"(p));
    return a;
}
static __device__ __forceinline__ void ldm4(uint32_t* r, uint32_t addr) {
    asm volatile("ldmatrix.sync.aligned.m8n8.x4.shared.b16 {%0,%1,%2,%3}, [%4];"
        : "=r"(r[0]), "=r"(r[1]), "=r"(r[2]), "=r"(r[3]) : "r"(addr));
}
static __device__ __forceinline__ void ldm4t(uint32_t* r, uint32_t addr) {
    asm volatile("ldmatrix.sync.aligned.m8n8.x4.trans.shared.b16 {%0,%1,%2,%3}, [%4];"
        : "=r"(r[0]), "=r"(r[1]), "=r"(r[2]), "=r"(r[3]) : "r"(addr));
}
static __device__ __forceinline__ void mma16816(float* c, const uint32_t* a,
                                                const uint32_t* b) {
    asm volatile("mma.sync.aligned.m16n8k16.row.col.f32.bf16.bf16.f32 "
        "{%0,%1,%2,%3}, {%4,%5,%6,%7}, {%8,%9}, {%0,%1,%2,%3};"
        : "+f"(c[0]), "+f"(c[1]), "+f"(c[2]), "+f"(c[3])
        : "r"(a[0]), "r"(a[1]), "r"(a[2]), "r"(a[3]), "r"(b[0]), "r"(b[1]));
}
static __device__ __forceinline__ void bsplit(float v, __nv_bfloat16* h, __nv_bfloat16* l) {
    __nv_bfloat16 hh = __float2bfloat16_rn(v);
    *h = hh;
    *l = __float2bfloat16_rn(v - __bfloat162float(hh));
}

// =======================================================================
// LayerNorm
// =======================================================================
__global__ void __launch_bounds__(256) ln_kernel(const float* __restrict__ x,
                                                 const float* __restrict__ gam,
                                                 const float* __restrict__ bet)
{
    int row = blockIdx.x;
    int t = threadIdx.x;
    const float4* xr = reinterpret_cast<const float4*>(x + (size_t)row * D_);
    float4 v = xr[t];
    float s  = v.x + v.y + v.z + v.w;
    float ss = v.x*v.x + v.y*v.y + v.z*v.z + v.w*v.w;
    __shared__ float rs[8], rss[8], stat[2];
    #pragma unroll
    for (int o = 16; o; o >>= 1) {
        s  += __shfl_xor_sync(0xffffffffu, s,  o);
        ss += __shfl_xor_sync(0xffffffffu, ss, o);
    }
    if ((t & 31) == 0) { rs[t >> 5] = s; rss[t >> 5] = ss; }
    __syncthreads();
    if (t == 0) {
        float S = 0.f, SS = 0.f;
        #pragma unroll
        for (int i = 0; i < 8; i++) { S += rs[i]; SS += rss[i]; }
        float mu  = S / (float)D_;
        float var = SS / (float)D_ - mu * mu;
        stat[0] = mu;
        stat[1] = rsqrtf(var + 1e-6f);
    }
    __syncthreads();
    float mu = stat[0], inv = stat[1];
    float4 g4 = reinterpret_cast<const float4*>(gam)[t];
    float4 b4 = reinterpret_cast<const float4*>(bet)[t];
    float4 o;
    o.x = (v.x - mu) * inv * g4.x + b4.x;
    o.y = (v.y - mu) * inv * g4.y + b4.y;
    o.z = (v.z - mu) * inv * g4.z + b4.z;
    o.w = (v.w - mu) * inv * g4.w + b4.w;
    reinterpret_cast<float4*>(g_xn + (size_t)row * D_)[t] = o;
}

// =======================================================================
// fp32 -> (hi, lo) bf16 split
// =======================================================================
__global__ void __launch_bounds__(256) split_kernel(const float* __restrict__ src,
                                                    __nv_bfloat16* __restrict__ hi,
                                                    __nv_bfloat16* __restrict__ lo,
                                                    int n4)
{
    int i = blockIdx.x * 256 + threadIdx.x;
    if (i >= n4) return;
    float4 v = reinterpret_cast<const float4*>(src)[i];
    __nv_bfloat16 h[4], l[4];
    bsplit(v.x, &h[0], &l[0]); bsplit(v.y, &h[1], &l[1]);
    bsplit(v.z, &h[2], &l[2]); bsplit(v.w, &h[3], &l[3]);
    ushort4 H, L;
    H.x = __bfloat16_as_ushort(h[0]); H.y = __bfloat16_as_ushort(h[1]);
    H.z = __bfloat16_as_ushort(h[2]); H.w = __bfloat16_as_ushort(h[3]);
    L.x = __bfloat16_as_ushort(l[0]); L.y = __bfloat16_as_ushort(l[1]);
    L.z = __bfloat16_as_ushort(l[2]); L.w = __bfloat16_as_ushort(l[3]);
    reinterpret_cast<ushort4*>(hi)[i] = H;
    reinterpret_cast<ushort4*>(lo)[i] = L;
}

// =======================================================================
// transpose + split: W[1024(K),1024(N)] row-major -> Wt[N][K] bf16 hi/lo
// =======================================================================
__global__ void __launch_bounds__(256) tsplit_kernel(const float* __restrict__ W,
                                                     __nv_bfloat16* __restrict__ th,
                                                     __nv_bfloat16* __restrict__ tl)
{
    __shared__ float sm[32][33];
    int c0 = blockIdx.x * 32, r0 = blockIdx.y * 32;
    int tx = threadIdx.x & 31, ty = threadIdx.x >> 5;
    #pragma unroll
    for (int k = 0; k < 32; k += 8)
        sm[ty + k][tx] = W[(size_t)(r0 + ty + k) * 1024 + c0 + tx];
    __syncthreads();
    #pragma unroll
    for (int k = 0; k < 32; k += 8) {
        float v = sm[tx][ty + k];
        int n = c0 + ty + k, kk = r0 + tx;
        __nv_bfloat16 h, l;
        bsplit(v, &h, &l);
        th[(size_t)n * 1024 + kk] = h;
        tl[(size_t)n * 1024 + kk] = l;
    }
}

// =======================================================================
// HMMA split-bf16 GEMM: C[M,1024] = A[M,1024] x W (+bias+resid)
// A (Ah,Al) row-major [m][k]; B (Bh,Bl) [n][k]. Tile 128x128, BK=32.
// 8 warps: wm = wid&3 (32 rows), wn = wid>>2 (64 cols).
// =======================================================================
#define GST 40   // smem row stride in bf16 (80 bytes)
__global__ void __launch_bounds__(256) mma_gemm(
    const __nv_bfloat16* __restrict__ Ah, const __nv_bfloat16* __restrict__ Al,
    const __nv_bfloat16* __restrict__ Bh, const __nv_bfloat16* __restrict__ Bl,
    float* __restrict__ C, int M,
    const float* __restrict__ bias, const float* __restrict__ resid)
{
    __shared__ __nv_bfloat16 smem[4 * 128 * GST];
    const uint32_t sb = smem_u32(smem);
    const uint32_t sAh = sb, sAl = sb + 10240, sBh = sb + 20480, sBl = sb + 30720;

    const int tid = threadIdx.x;
    const int wid = tid >> 5, lane = tid & 31;
    const int wm = wid & 3, wn = wid >> 2;
    const int m0 = blockIdx.y * 128, n0 = blockIdx.x * 128;

    float acc[2][8][4];
    #pragma unroll
    for (int i = 0; i < 2; i++)
        #pragma unroll
        for (int j = 0; j < 8; j++)
            #pragma unroll
            for (int c = 0; c < 4; c++) acc[i][j][c] = 0.f;

    const int lr = tid >> 2;            // 0..63 (two rows per pass)
    const int lc = (tid & 3) * 16;      // byte col

    for (int kt = 0; kt < 1024; kt += 32) {
        __syncthreads();
        #pragma unroll
        for (int t = 0; t < 2; t++) {
            int r = lr + t * 64;
            uint32_t so = (uint32_t)r * 80 + lc;
            int arow = m0 + r;
            uint4 vh = make_uint4(0,0,0,0), vl = make_uint4(0,0,0,0);
            if (arow < M) {
                size_t go = (size_t)arow * 1024 + kt + (lc >> 1);
                vh = *reinterpret_cast<const uint4*>(Ah + go);
                vl = *reinterpret_cast<const uint4*>(Al + go);
            }
            *reinterpret_cast<uint4*>(smem) = *reinterpret_cast<uint4*>(smem); // keep compiler honest
            *reinterpret_cast<uint4*>((char*)smem + so)         = vh;
            *reinterpret_cast<uint4*>((char*)smem + 10240 + so) = vl;
            size_t gb = (size_t)(n0 + r) * 1024 + kt + (lc >> 1);
            uint4 wh = *reinterpret_cast<const uint4*>(Bh + gb);
            uint4 wl = *reinterpret_cast<const uint4*>(Bl + gb);
            *reinterpret_cast<uint4*>((char*)smem + 20480 + so) = wh;
            *reinterpret_cast<uint4*>((char*)smem + 30720 + so) = wl;
        }
        __syncthreads();

        #pragma unroll
        for (int ks = 0; ks < 2; ks++) {
            uint32_t a_h[2][4], a_l[2][4], b_h[4][4], b_l[4][4];
            #pragma unroll
            for (int mt = 0; mt < 2; mt++) {
                int row = wm * 32 + mt * 16 + (lane & 15);
                uint32_t off = (uint32_t)row * 80 + ks * 32 + ((lane >> 4) << 4);
                ldm4(a_h[mt], sAh + off);
                ldm4(a_l[mt], sAl + off);
            }
            #pragma unroll
            for (int p = 0; p < 4; p++) {
                int row = wn * 64 + p * 16 + (lane & 7) + ((lane >> 4) & 1) * 8;
                uint32_t off = (uint32_t)row * 80 + ks * 32 + (((lane >> 3) & 1) << 4);
                ldm4(b_h[p], sBh + off);
                ldm4(b_l[p], sBl + off);
            }
            #pragma unroll
            for (int mt = 0; mt < 2; mt++)
                #pragma unroll
                for (int nt = 0; nt < 8; nt++) {
                    uint32_t* bh = &b_h[nt >> 1][(nt & 1) * 2];
                    uint32_t* bl = &b_l[nt >> 1][(nt & 1) * 2];
                    mma16816(acc[mt][nt], a_h[mt], bh);
                    mma16816(acc[mt][nt], a_h[mt], bl);
                    mma16816(acc[mt][nt], a_l[mt], bh);
                }
        }
    }

    // epilogue
    #pragma unroll
    for (int mt = 0; mt < 2; mt++) {
        #pragma unroll
        for (int half = 0; half < 2; half++) {
            int row = m0 + wm * 32 + mt * 16 + (lane >> 2) + half * 8;
            if (row >= M) continue;
            #pragma unroll
            for (int nt = 0; nt < 8; nt++) {
                int col = n0 + wn * 64 + nt * 8 + (lane & 3) * 2;
                float2 v;
                v.x = acc[mt][nt][half * 2 + 0];
                v.y = acc[mt][nt][half * 2 + 1];
                if (bias)  { v.x += bias[col]; v.y += bias[col + 1]; }
                size_t go = (size_t)row * 1024 + col;
                if (resid) {
                    float2 rv = *reinterpret_cast<const float2*>(resid + go);
                    v.x += rv.x; v.y += rv.y;
                }
                *reinterpret_cast<float2*>(C + go) = v;
            }
        }
    }
}

// =======================================================================
// segment fix-up: rows l in [1027,1030) use weight set 1 (exact fp32)
// =======================================================================
__global__ void __launch_bounds__(256) seg_fix(const float* __restrict__ wq1,
                                               const float* __restrict__ wk1,
                                               const float* __restrict__ wv1)
{
    int which = blockIdx.y;
    const float* W = (which == 0) ? wq1 : (which == 1) ? wk1 : wv1;
    float* O       = (which == 0) ? g_q : (which == 1) ? g_k : g_v;
    int batch = blockIdx.x / 3, s = blockIdx.x % 3;
    int row = batch * L_ + (L_ - 3) + s;

    __shared__ float xs[1024];
    for (int i = threadIdx.x; i < 1024; i += 256) xs[i] = g_xn[(size_t)row * 1024 + i];
    __syncthreads();

    float a0 = 0.f, a1 = 0.f, a2 = 0.f, a3 = 0.f;
    const float* Wc = W + threadIdx.x;
    for (int k = 0; k < 1024; k++) {
        float xv = xs[k];
        const float* wr = Wc + (size_t)k * 1024;
        a0 += xv * wr[0];
        a1 += xv * wr[256];
        a2 += xv * wr[512];
        a3 += xv * wr[768];
    }
    float* o = O + (size_t)row * 1024 + threadIdx.x;
    o[0] = a0; o[256] = a1; o[512] = a2; o[768] = a3;
}

// =======================================================================
// tensorized fused attention
// block = (qt, h, b): 32 query rows, 256 threads (8 warps)
// smem: S 32x1032 f32 | Qh/Ql 32x72 bf16 | Kh/Kl (=Vh/Vl) 128x72 | Ph/Pl 32x136
// =======================================================================
#define SST 1032
#define QVST 72      // bf16 stride for 64-wide tiles (144B)
#define PST 136      // bf16 stride for 128-wide tiles (272B)
#define OFF_Q  132096
#define OFF_K  (OFF_Q + 2*32*QVST*2)        // 141312
#define OFF_P  (OFF_K + 2*128*QVST*2)       // 178176
#define ATTN_SMEM (OFF_P + 2*32*PST*2)      // 195584

__global__ void __launch_bounds__(256) attn_mma(float* __restrict__ attn_out)
{
    extern __shared__ char sm[];
    float* S = reinterpret_cast<float*>(sm);
    __nv_bfloat16* Qh = reinterpret_cast<__nv_bfloat16*>(sm + OFF_Q);
    __nv_bfloat16* Ql = Qh + 32 * QVST;
    __nv_bfloat16* Kh = reinterpret_cast<__nv_bfloat16*>(sm + OFF_K);
    __nv_bfloat16* Kl = Kh + 128 * QVST;
    __nv_bfloat16* Ph = reinterpret_cast<__nv_bfloat16*>(sm + OFF_P);
    __nv_bfloat16* Pl = Ph + 32 * PST;
    const uint32_t uQh = smem_u32(Qh), uQl = smem_u32(Ql);
    const uint32_t uKh = smem_u32(Kh), uKl = smem_u32(Kl);
    const uint32_t uPh = smem_u32(Ph), uPl = smem_u32(Pl);

    const int tid = threadIdx.x;
    const int wid = tid >> 5, lane = tid & 31;
    const int wm = wid & 1, wn = wid >> 1;      // 2 (M) x 4 (N)
    const int qt = blockIdx.x, h = blockIdx.y, b = blockIdx.z;
    const int q0 = qt * 32;
    const size_t headq = (size_t)b * L_ * 1024 + h * 64;

    // ---- load Q (scaled by 0.125), split ----
    #pragma unroll
    for (int t = 0; t < 2; t++) {
        int idx = tid + t * 256;              // 0..511
        int r = idx >> 4, c4 = (idx & 15) * 4;
        int l = q0 + r;
        float4 v = make_float4(0.f, 0.f, 0.f, 0.f);
        if (l < L_) v = *reinterpret_cast<const float4*>(g_q + headq + (size_t)l * 1024 + c4);
        __nv_bfloat16 hh[4], ll[4];
        bsplit(v.x * 0.125f, &hh[0], &ll[0]);
        bsplit(v.y * 0.125f, &hh[1], &ll[1]);
        bsplit(v.z * 0.125f, &hh[2], &ll[2]);
        bsplit(v.w * 0.125f, &hh[3], &ll[3]);
        *reinterpret_cast<ushort4*>(Qh + r * QVST + c4) = make_ushort4(
            __bfloat16_as_ushort(hh[0]), __bfloat16_as_ushort(hh[1]),
            __bfloat16_as_ushort(hh[2]), __bfloat16_as_ushort(hh[3]));
        *reinterpret_cast<ushort4*>(Ql + r * QVST + c4) = make_ushort4(
            __bfloat16_as_ushort(ll[0]), __bfloat16_as_ushort(ll[1]),
            __bfloat16_as_ushort(ll[2]), __bfloat16_as_ushort(ll[3]));
    }

    // ---- phase 1: S = Q.K^T ----
    for (int kt = 0; kt < L_; kt += 128) {
        __syncthreads();
        #pragma unroll
        for (int t = 0; t < 8; t++) {
            int idx = tid + t * 256;          // 0..2047
            int r = idx >> 4, c4 = (idx & 15) * 4;
            int l = kt + r;
            float4 v = make_float4(0.f, 0.f, 0.f, 0.f);
            if (l < L_) v = *reinterpret_cast<const float4*>(g_k + headq + (size_t)l * 1024 + c4);
            __nv_bfloat16 hh[4], ll[4];
            bsplit(v.x, &hh[0], &ll[0]); bsplit(v.y, &hh[1], &ll[1]);
            bsplit(v.z, &hh[2], &ll[2]); bsplit(v.w, &hh[3], &ll[3]);
            *reinterpret_cast<ushort4*>(Kh + r * QVST + c4) = make_ushort4(
                __bfloat16_as_ushort(hh[0]), __bfloat16_as_ushort(hh[1]),
                __bfloat16_as_ushort(hh[2]), __bfloat16_as_ushort(hh[3]));
            *reinterpret_cast<ushort4*>(Kl + r * QVST + c4) = make_ushort4(
                __bfloat16_as_ushort(ll[0]), __bfloat16_as_ushort(ll[1]),
                __bfloat16_as_ushort(ll[2]), __bfloat16_as_ushort(ll[3]));
        }
        __syncthreads();

        float acc[4][4];
        #pragma unroll
        for (int i = 0; i < 4; i++)
            #pragma unroll
            for (int c = 0; c < 4; c++) acc[i][c] = 0.f;

        #pragma unroll
        for (int ks = 0; ks < 4; ks++) {
            uint32_t qh[4], ql[4], kh[2][4], kl[2][4];
            {
                int row = wm * 16 + (lane & 15);
                uint32_t off = (uint32_t)row * 144 + ks * 32 + ((lane >> 4) << 4);
                ldm4(qh, uQh + off);
                ldm4(ql, uQl + off);
            }
            #pragma unroll
            for (int p = 0; p < 2; p++) {
                int row = wn * 32 + p * 16 + (lane & 7) + ((lane >> 4) & 1) * 8;
                uint32_t off = (uint32_t)row * 144 + ks * 32 + (((lane >> 3) & 1) << 4);
                ldm4(kh[p], uKh + off);
                ldm4(kl[p], uKl + off);
            }
            #pragma unroll
            for (int nt = 0; nt < 4; nt++) {
                uint32_t* bh = &kh[nt >> 1][(nt & 1) * 2];
                uint32_t* bl = &kl[nt >> 1][(nt & 1) * 2];
                mma16816(acc[nt], qh, bh);
                mma16816(acc[nt], qh, bl);
                mma16816(acc[nt], ql, bh);
            }
        }

        int r0 = wm * 16 + (lane >> 2);
        #pragma unroll
        for (int nt = 0; nt < 4; nt++) {
            int col = kt + wn * 32 + nt * 8 + (lane & 3) * 2;
            if (col < L_)     S[r0 * SST + col]           = acc[nt][0];
            if (col + 1 < L_) S[r0 * SST + col + 1]       = acc[nt][1];
            if (col < L_)     S[(r0 + 8) * SST + col]     = acc[nt][2];
            if (col + 1 < L_) S[(r0 + 8) * SST + col + 1] = acc[nt][3];
        }
    }
    __syncthreads();

    // ---- softmax + attn write (warp per 4 rows) ----
    for (int r = wid * 4; r < wid * 4 + 4; r++) {
        int l = q0 + r;
        if (l >= L_) continue;
        float* Sr = S + r * SST;
        float m = -1e30f;
        for (int j = lane; j < L_; j += 32) m = fmaxf(m, Sr[j]);
        #pragma unroll
        for (int o = 16; o; o >>= 1) m = fmaxf(m, __shfl_xor_sync(0xffffffffu, m, o));
        float ssum = 0.f;
        for (int j = lane; j < L_; j += 32) { float e = __expf(Sr[j] - m); Sr[j] = e; ssum += e; }
        #pragma unroll
        for (int o = 16; o; o >>= 1) ssum += __shfl_xor_sync(0xffffffffu, ssum, o);
        float inv = 1.f / ssum;
        size_t abase = ((size_t)(b * H_ + h) * L_ + l) * L_;
        for (int j = lane; j < L_; j += 32) {
            float p = Sr[j] * inv;
            Sr[j] = p;
            if (attn_out) attn_out[abase + j] = p;
        }
    }

    // ---- phase 2: O = P.V ----
    float acc2[2][4];
    #pragma unroll
    for (int i = 0; i < 2; i++)
        #pragma unroll
        for (int c = 0; c < 4; c++) acc2[i][c] = 0.f;

    for (int kt = 0; kt < L_; kt += 128) {
        __syncthreads();
        // load V tile (reuse K buffers)
        #pragma unroll
        for (int t = 0; t < 8; t++) {
            int idx = tid + t * 256;
            int r = idx >> 4, c4 = (idx & 15) * 4;
            int l = kt + r;
            float4 v = make_float4(0.f, 0.f, 0.f, 0.f);
            if (l < L_) v = *reinterpret_cast<const float4*>(g_v + headq + (size_t)l * 1024 + c4);
            __nv_bfloat16 hh[4], ll[4];
            bsplit(v.x, &hh[0], &ll[0]); bsplit(v.y, &hh[1], &ll[1]);
            bsplit(v.z, &hh[2], &ll[2]); bsplit(v.w, &hh[3], &ll[3]);
            *reinterpret_cast<ushort4*>(Kh + r * QVST + c4) = make_ushort4(
                __bfloat16_as_ushort(hh[0]), __bfloat16_as_ushort(hh[1]),
                __bfloat16_as_ushort(hh[2]), __bfloat16_as_ushort(hh[3]));
            *reinterpret_cast<ushort4*>(Kl + r * QVST + c4) = make_ushort4(
                __bfloat16_as_ushort(ll[0]), __bfloat16_as_ushort(ll[1]),
                __bfloat16_as_ushort(ll[2]), __bfloat16_as_ushort(ll[3]));
        }
        // convert P chunk
        #pragma unroll
        for (int t = 0; t < 16; t++) {
            int idx = tid + t * 256;          // 0..4095
            int r = idx >> 7, c = idx & 127;
            int col = kt + c;
            float p = (col < L_) ? S[r * SST + col] : 0.f;
            __nv_bfloat16 hh, ll;
            bsplit(p, &hh, &ll);
            Ph[r * PST + c] = hh;
            Pl[r * PST + c] = ll;
        }
        __syncthreads();

        #pragma unroll
        for (int ks = 0; ks < 8; ks++) {
            uint32_t ph[4], pl[4], vh[4], vl[4];
            {
                int row = wm * 16 + (lane & 15);
                uint32_t off = (uint32_t)row * 272 + ks * 32 + ((lane >> 4) << 4);
                ldm4(ph, uPh + off);
                ldm4(pl, uPl + off);
            }
            {
                int row = ks * 16 + (lane & 15);
                uint32_t off = (uint32_t)row * 144 + wn * 32 + ((lane >> 4) << 4);
                ldm4t(vh, uKh + off);
                ldm4t(vl, uKl + off);
            }
            #pragma unroll
            for (int nt = 0; nt < 2; nt++) {
                mma16816(acc2[nt], ph, &vh[nt * 2]);
                mma16816(acc2[nt], ph, &vl[nt * 2]);
                mma16816(acc2[nt], pl, &vh[nt * 2]);
            }
        }
    }

    // output
    #pragma unroll
    for (int half = 0; half < 2; half++) {
        int r = wm * 16 + (lane >> 2) + half * 8;
        int l = q0 + r;
        if (l >= L_) continue;
        #pragma unroll
        for (int nt = 0; nt < 2; nt++) {
            int d = wn * 16 + nt * 8 + (lane & 3) * 2;
            float2 v;
            v.x = acc2[nt][half * 2 + 0];
            v.y = acc2[nt][half * 2 + 1];
            *reinterpret_cast<float2*>(g_ao + headq + (size_t)l * 1024 + d) = v;
        }
    }
}

// =======================================================================
// launch
// =======================================================================
extern "C" void kernel_launch(void* const* d_in, const int* in_sizes, int n_in,
                              void* d_out, int out_size)
{
    const float* x    = (const float*)d_in[0];
    const float* wq0  = (const float*)d_in[1];
    const float* wq1  = (const float*)d_in[2];
    const float* wk0  = (const float*)d_in[3];
    const float* wk1  = (const float*)d_in[4];
    const float* wv0  = (const float*)d_in[5];
    const float* wv1  = (const float*)d_in[6];
    const float* fc_w = (const float*)d_in[7];
    const float* fc_b = (const float*)d_in[8];
    const float* ln_g = (const float*)d_in[9];
    const float* ln_b = (const float*)d_in[10];
    float* out = (float*)d_out;

    float *p_xn, *p_q, *p_k, *p_v, *p_ao;
    __nv_bfloat16 *p_sh, *p_sl, *p_wth, *p_wtl;
    cudaGetSymbolAddress((void**)&p_xn, g_xn);
    cudaGetSymbolAddress((void**)&p_q,  g_q);
    cudaGetSymbolAddress((void**)&p_k,  g_k);
    cudaGetSymbolAddress((void**)&p_v,  g_v);
    cudaGetSymbolAddress((void**)&p_ao, g_ao);
    cudaGetSymbolAddress((void**)&p_sh, g_sh);
    cudaGetSymbolAddress((void**)&p_sl, g_sl);
    cudaGetSymbolAddress((void**)&p_wth, g_wth);
    cudaGetSymbolAddress((void**)&p_wtl, g_wtl);

    float* attn_ptr = ((size_t)out_size >= OUT_ELEMS + ATTN_ELEMS)
                        ? (out + OUT_ELEMS) : nullptr;

    // 1) LayerNorm
    ln_kernel<<<M_, 256>>>(x, ln_g, ln_b);

    // 2) split xn ; transpose+split weights
    int n4 = M_ * 1024 / 4;
    split_kernel<<<(n4 + 255) / 256, 256>>>(p_xn, p_sh, p_sl, n4);
    dim3 tg(32, 32);
    const size_t WSZ = 1024 * 1024;
    tsplit_kernel<<<tg, 256>>>(wq0,  p_wth + 0 * WSZ, p_wtl + 0 * WSZ);
    tsplit_kernel<<<tg, 256>>>(wk0,  p_wth + 1 * WSZ, p_wtl + 1 * WSZ);
    tsplit_kernel<<<tg, 256>>>(wv0,  p_wth + 2 * WSZ, p_wtl + 2 * WSZ);
    tsplit_kernel<<<tg, 256>>>(fc_w, p_wth + 3 * WSZ, p_wtl + 3 * WSZ);

    // 3) Q/K/V projections (HMMA split-bf16)
    dim3 gg(8, (M_ + 127) / 128);
    mma_gemm<<<gg, 256>>>(p_sh, p_sl, p_wth + 0 * WSZ, p_wtl + 0 * WSZ, p_q, M_, nullptr, nullptr);
    mma_gemm<<<gg, 256>>>(p_sh, p_sl, p_wth + 1 * WSZ, p_wtl + 1 * WSZ, p_k, M_, nullptr, nullptr);
    mma_gemm<<<gg, 256>>>(p_sh, p_sl, p_wth + 2 * WSZ, p_wtl + 2 * WSZ, p_v, M_, nullptr, nullptr);

    // 4) exact fp32 fix for the 24 weight-set-1 rows
    seg_fix<<<dim3(24, 3), 256>>>(wq1, wk1, wv1);

    // 5) tensorized attention
    cudaFuncSetAttribute(attn_mma, cudaFuncAttributeMaxDynamicSharedMemorySize, ATTN_SMEM);
    attn_mma<<<dim3((L_ + 31) / 32, H_, B_), 256, ATTN_SMEM>>>(attn_ptr);

    // 6) FC (+bias+residual)
    split_kernel<<<(n4 + 255) / 256, 256>>>(p_ao, p_sh, p_sl, n4);
    mma_gemm<<<gg, 256>>>(p_sh, p_sl, p_wth + 3 * WSZ, p_wtl + 3 * WSZ, out, M_, fc_b, x);
}

// round 7
// speedup vs baseline: 2.5061x; 1.0762x over previous
#include <cuda_runtime.h>
#include <cuda_bf16.h>
#include <cstdint>

#define B_ 8
#define L_ 1030
#define D_ 1024
#define H_ 16
#define M_ (B_*L_)          // 8240
#define WSZ (1024*1024)

typedef __nv_bfloat16 bf;

static const size_t OUT_ELEMS  = (size_t)M_ * D_;              // 8,437,760
static const size_t ATTN_ELEMS = (size_t)B_ * H_ * L_ * L_;    // 135,795,200

// Scratch (device globals: no runtime allocation allowed)
__device__ float g_xn[M_*D_];                 // exact LN output (for seg_fix)
__device__ bf g_xh[M_*D_],  g_xl[M_*D_];      // split LN output (GEMM A)
__device__ bf g_qh[M_*D_],  g_ql[M_*D_];      // split Q (pre-scaled by 0.125)
__device__ bf g_kh[M_*D_],  g_kl[M_*D_];
__device__ bf g_vh[M_*D_],  g_vl[M_*D_];
__device__ bf g_aoh[M_*D_], g_aol[M_*D_];     // split attention output
__device__ bf g_wth[4*WSZ], g_wtl[4*WSZ];     // transposed+split weights [N][K]

// =======================================================================
// helpers
// =======================================================================
static __device__ __forceinline__ uint32_t smem_u32(const void* p) {
    uint32_t a;
    asm("{ .reg .u64 t; cvta.to.shared.u64 t, %1; cvt.u32.u64 %0, t; }"
        : "=r"(a) : "l"(p));
    return a;
}
static __device__ __forceinline__ void ldm4(uint32_t* r, uint32_t addr) {
    asm volatile("ldmatrix.sync.aligned.m8n8.x4.shared.b16 {%0,%1,%2,%3}, [%4];"
        : "=r"(r[0]), "=r"(r[1]), "=r"(r[2]), "=r"(r[3]) : "r"(addr));
}
static __device__ __forceinline__ void ldm4t(uint32_t* r, uint32_t addr) {
    asm volatile("ldmatrix.sync.aligned.m8n8.x4.trans.shared.b16 {%0,%1,%2,%3}, [%4];"
        : "=r"(r[0]), "=r"(r[1]), "=r"(r[2]), "=r"(r[3]) : "r"(addr));
}
static __device__ __forceinline__ void mma16816(float* c, const uint32_t* a,
                                                const uint32_t* b) {
    asm volatile("mma.sync.aligned.m16n8k16.row.col.f32.bf16.bf16.f32 "
        "{%0,%1,%2,%3}, {%4,%5,%6,%7}, {%8,%9}, {%0,%1,%2,%3};"
        : "+f"(c[0]), "+f"(c[1]), "+f"(c[2]), "+f"(c[3])
        : "r"(a[0]), "r"(a[1]), "r"(a[2]), "r"(a[3]), "r"(b[0]), "r"(b[1]));
}
static __device__ __forceinline__ void bsplit(float v, bf* h, bf* l) {
    bf hh = __float2bfloat16_rn(v);
    *h = hh;
    *l = __float2bfloat16_rn(v - __bfloat162float(hh));
}
static __device__ __forceinline__ void cpa(uint32_t dst, const void* src, int sz) {
    asm volatile("cp.async.cg.shared.global [%0], [%1], 16, %2;"
                 :: "r"(dst), "l"(src), "r"(sz));
}
static __device__ __forceinline__ void cpa_commit() {
    asm volatile("cp.async.commit_group;");
}

// =======================================================================
// LayerNorm: writes exact f32 xn AND split bf16 (xh, xl)
// =======================================================================
__global__ void __launch_bounds__(256) ln_kernel(const float* __restrict__ x,
                                                 const float* __restrict__ gam,
                                                 const float* __restrict__ bet)
{
    int row = blockIdx.x;
    int t = threadIdx.x;
    const float4* xr = reinterpret_cast<const float4*>(x + (size_t)row * D_);
    float4 v = xr[t];
    float s  = v.x + v.y + v.z + v.w;
    float ss = v.x*v.x + v.y*v.y + v.z*v.z + v.w*v.w;
    __shared__ float rs[8], rss[8], stat[2];
    #pragma unroll
    for (int o = 16; o; o >>= 1) {
        s  += __shfl_xor_sync(0xffffffffu, s,  o);
        ss += __shfl_xor_sync(0xffffffffu, ss, o);
    }
    if ((t & 31) == 0) { rs[t >> 5] = s; rss[t >> 5] = ss; }
    __syncthreads();
    if (t == 0) {
        float S = 0.f, SS = 0.f;
        #pragma unroll
        for (int i = 0; i < 8; i++) { S += rs[i]; SS += rss[i]; }
        float mu  = S / (float)D_;
        float var = SS / (float)D_ - mu * mu;
        stat[0] = mu;
        stat[1] = rsqrtf(var + 1e-6f);
    }
    __syncthreads();
    float mu = stat[0], inv = stat[1];
    float4 g4 = reinterpret_cast<const float4*>(gam)[t];
    float4 b4 = reinterpret_cast<const float4*>(bet)[t];
    float4 o;
    o.x = (v.x - mu) * inv * g4.x + b4.x;
    o.y = (v.y - mu) * inv * g4.y + b4.y;
    o.z = (v.z - mu) * inv * g4.z + b4.z;
    o.w = (v.w - mu) * inv * g4.w + b4.w;
    size_t base = (size_t)row * D_ + t * 4;
    *reinterpret_cast<float4*>(g_xn + base) = o;
    bf h[4], l[4];
    bsplit(o.x, &h[0], &l[0]); bsplit(o.y, &h[1], &l[1]);
    bsplit(o.z, &h[2], &l[2]); bsplit(o.w, &h[3], &l[3]);
    *reinterpret_cast<ushort4*>(g_xh + base) = make_ushort4(
        __bfloat16_as_ushort(h[0]), __bfloat16_as_ushort(h[1]),
        __bfloat16_as_ushort(h[2]), __bfloat16_as_ushort(h[3]));
    *reinterpret_cast<ushort4*>(g_xl + base) = make_ushort4(
        __bfloat16_as_ushort(l[0]), __bfloat16_as_ushort(l[1]),
        __bfloat16_as_ushort(l[2]), __bfloat16_as_ushort(l[3]));
}

// =======================================================================
// transpose + split: W[1024(K),1024(N)] row-major -> Wt[N][K] bf16 hi/lo
// =======================================================================
__global__ void __launch_bounds__(256) tsplit_kernel(const float* __restrict__ W,
                                                     bf* __restrict__ th,
                                                     bf* __restrict__ tl)
{
    __shared__ float sm[32][33];
    int c0 = blockIdx.x * 32, r0 = blockIdx.y * 32;
    int tx = threadIdx.x & 31, ty = threadIdx.x >> 5;
    #pragma unroll
    for (int k = 0; k < 32; k += 8)
        sm[ty + k][tx] = W[(size_t)(r0 + ty + k) * 1024 + c0 + tx];
    __syncthreads();
    #pragma unroll
    for (int k = 0; k < 32; k += 8) {
        float v = sm[tx][ty + k];
        int n = c0 + ty + k, kk = r0 + tx;
        bf h, l;
        bsplit(v, &h, &l);
        th[(size_t)n * 1024 + kk] = h;
        tl[(size_t)n * 1024 + kk] = l;
    }
}

// =======================================================================
// HMMA split-bf16 GEMM, cp.async double-buffered.
// Tile 128x128, BK=32, 8 warps (4 M x 2 N), warp tile 32x64.
// Epilogue: f32 (+bias+resid) if Cf!=null, else split-bf16 x scale.
// smem: 2 stages x (Ah|Al|Bh|Bl), each 128 x 40 bf16 (10240 B) = 81920 B.
// =======================================================================
#define STG_SZ 40960
__global__ void __launch_bounds__(256) mma_gemm(
    const bf* __restrict__ Ah, const bf* __restrict__ Al,
    const bf* __restrict__ Bh_, const bf* __restrict__ Bl_,
    float* __restrict__ Cf, const float* __restrict__ bias,
    const float* __restrict__ resid,
    bf* Q_h, bf* Q_l, bf* K_h, bf* K_l, bf* V_h, bf* V_l,
    int M)
{
    extern __shared__ char smem[];
    const uint32_t sb = smem_u32(smem);

    const int tid = threadIdx.x;
    const int wid = tid >> 5, lane = tid & 31;
    const int wm = wid & 3, wn = wid >> 2;
    const int m0 = blockIdx.y * 128, n0 = blockIdx.x * 128;
    const int z = blockIdx.z;

    const bf* Bh = Bh_ + (size_t)z * WSZ;
    const bf* Bl = Bl_ + (size_t)z * WSZ;
    bf* Oh = (z == 0) ? Q_h : (z == 1) ? K_h : V_h;
    bf* Ol = (z == 0) ? Q_l : (z == 1) ? K_l : V_l;
    const float scale = (z == 0) ? 0.125f : 1.0f;

    float acc[2][8][4];
    #pragma unroll
    for (int i = 0; i < 2; i++)
        #pragma unroll
        for (int j = 0; j < 8; j++)
            #pragma unroll
            for (int c = 0; c < 4; c++) acc[i][j][c] = 0.f;

    const int lr = tid >> 2;            // 0..63
    const int lc = (tid & 3) * 16;      // byte col within 64B row

    // ---- prefetch helper (stage stg, k offset kt) ----
    auto prefetch = [&](int kt, int stg) {
        uint32_t base = sb + stg * STG_SZ;
        #pragma unroll
        for (int t = 0; t < 2; t++) {
            int r = lr + t * 64;
            uint32_t so = (uint32_t)r * 80 + lc;
            int arow = m0 + r;
            int szA = (arow < M) ? 16 : 0;
            int arow2 = (arow < M) ? arow : 0;
            const char* pAh = (const char*)(Ah + (size_t)arow2 * 1024 + kt) + lc;
            const char* pAl = (const char*)(Al + (size_t)arow2 * 1024 + kt) + lc;
            cpa(base + so,         pAh, szA);
            cpa(base + 10240 + so, pAl, szA);
            const char* pBh = (const char*)(Bh + (size_t)(n0 + r) * 1024 + kt) + lc;
            const char* pBl = (const char*)(Bl + (size_t)(n0 + r) * 1024 + kt) + lc;
            cpa(base + 20480 + so, pBh, 16);
            cpa(base + 30720 + so, pBl, 16);
        }
        cpa_commit();
    };

    prefetch(0, 0);

    for (int it = 0; it < 32; it++) {
        if (it + 1 < 32) {
            prefetch((it + 1) * 32, (it + 1) & 1);
            asm volatile("cp.async.wait_group 1;");
        } else {
            asm volatile("cp.async.wait_group 0;");
        }
        __syncthreads();

        uint32_t st = sb + (it & 1) * STG_SZ;
        uint32_t sAh = st, sAl = st + 10240, sBh = st + 20480, sBl = st + 30720;

        #pragma unroll
        for (int ks = 0; ks < 2; ks++) {
            uint32_t a_h[2][4], a_l[2][4], b_h[4][4], b_l[4][4];
            #pragma unroll
            for (int mt = 0; mt < 2; mt++) {
                int row = wm * 32 + mt * 16 + (lane & 15);
                uint32_t off = (uint32_t)row * 80 + ks * 32 + ((lane >> 4) << 4);
                ldm4(a_h[mt], sAh + off);
                ldm4(a_l[mt], sAl + off);
            }
            #pragma unroll
            for (int p = 0; p < 4; p++) {
                int row = wn * 64 + p * 16 + (lane & 7) + ((lane >> 4) & 1) * 8;
                uint32_t off = (uint32_t)row * 80 + ks * 32 + (((lane >> 3) & 1) << 4);
                ldm4(b_h[p], sBh + off);
                ldm4(b_l[p], sBl + off);
            }
            #pragma unroll
            for (int mt = 0; mt < 2; mt++)
                #pragma unroll
                for (int nt = 0; nt < 8; nt++) {
                    uint32_t* bh = &b_h[nt >> 1][(nt & 1) * 2];
                    uint32_t* bl = &b_l[nt >> 1][(nt & 1) * 2];
                    mma16816(acc[mt][nt], a_h[mt], bh);
                    mma16816(acc[mt][nt], a_h[mt], bl);
                    mma16816(acc[mt][nt], a_l[mt], bh);
                }
        }
        __syncthreads();
    }

    // ---- epilogue ----
    #pragma unroll
    for (int mt = 0; mt < 2; mt++) {
        #pragma unroll
        for (int half = 0; half < 2; half++) {
            int row = m0 + wm * 32 + mt * 16 + (lane >> 2) + half * 8;
            if (row >= M) continue;
            #pragma unroll
            for (int nt = 0; nt < 8; nt++) {
                int col = n0 + wn * 64 + nt * 8 + (lane & 3) * 2;
                float vx = acc[mt][nt][half * 2 + 0];
                float vy = acc[mt][nt][half * 2 + 1];
                size_t go = (size_t)row * 1024 + col;
                if (Cf) {
                    if (bias) { vx += bias[col]; vy += bias[col + 1]; }
                    float2 v2;
                    v2.x = vx; v2.y = vy;
                    if (resid) {
                        float2 rv = *reinterpret_cast<const float2*>(resid + go);
                        v2.x += rv.x; v2.y += rv.y;
                    }
                    *reinterpret_cast<float2*>(Cf + go) = v2;
                } else {
                    vx *= scale; vy *= scale;
                    bf hx, lx, hy, ly;
                    bsplit(vx, &hx, &lx);
                    bsplit(vy, &hy, &ly);
                    *reinterpret_cast<ushort2*>(Oh + go) = make_ushort2(
                        __bfloat16_as_ushort(hx), __bfloat16_as_ushort(hy));
                    *reinterpret_cast<ushort2*>(Ol + go) = make_ushort2(
                        __bfloat16_as_ushort(lx), __bfloat16_as_ushort(ly));
                }
            }
        }
    }
}

// =======================================================================
// segment fix-up: rows l in [1027,1030) use weight set 1 (exact fp32,
// then split to the bf16 hi/lo buffers; q gets the 0.125 scale)
// =======================================================================
__global__ void __launch_bounds__(256) seg_fix(const float* __restrict__ wq1,
                                               const float* __restrict__ wk1,
                                               const float* __restrict__ wv1)
{
    int which = blockIdx.y;
    const float* W = (which == 0) ? wq1 : (which == 1) ? wk1 : wv1;
    bf* Oh = (which == 0) ? g_qh : (which == 1) ? g_kh : g_vh;
    bf* Ol = (which == 0) ? g_ql : (which == 1) ? g_kl : g_vl;
    float scale = (which == 0) ? 0.125f : 1.0f;
    int batch = blockIdx.x / 3, s = blockIdx.x % 3;
    int row = batch * L_ + (L_ - 3) + s;

    __shared__ float xs[1024];
    for (int i = threadIdx.x; i < 1024; i += 256) xs[i] = g_xn[(size_t)row * 1024 + i];
    __syncthreads();

    float a[4] = {0.f, 0.f, 0.f, 0.f};
    const float* Wc = W + threadIdx.x;
    for (int k = 0; k < 1024; k++) {
        float xv = xs[k];
        const float* wr = Wc + (size_t)k * 1024;
        a[0] += xv * wr[0];
        a[1] += xv * wr[256];
        a[2] += xv * wr[512];
        a[3] += xv * wr[768];
    }
    #pragma unroll
    for (int j = 0; j < 4; j++) {
        float v = a[j] * scale;
        bf h, l;
        bsplit(v, &h, &l);
        size_t off = (size_t)row * 1024 + threadIdx.x + j * 256;
        Oh[off] = h;
        Ol[off] = l;
    }
}

// =======================================================================
// tensorized fused attention (inputs pre-split bf16)
// block = (qt, h, b): 32 query rows, 256 threads (8 warps)
// =======================================================================
#define SST 1032
#define QVST 72
#define PST 136
#define OFF_Q  132096
#define OFF_K  (OFF_Q + 2*32*QVST*2)
#define OFF_P  (OFF_K + 2*128*QVST*2)
#define ATTN_SMEM (OFF_P + 2*32*PST*2)

__global__ void __launch_bounds__(256) attn_mma(float* __restrict__ attn_out)
{
    extern __shared__ char sm[];
    float* S = reinterpret_cast<float*>(sm);
    bf* Qh = reinterpret_cast<bf*>(sm + OFF_Q);
    bf* Ql = Qh + 32 * QVST;
    bf* Kh = reinterpret_cast<bf*>(sm + OFF_K);
    bf* Kl = Kh + 128 * QVST;
    bf* Ph = reinterpret_cast<bf*>(sm + OFF_P);
    bf* Pl = Ph + 32 * PST;
    const uint32_t uQh = smem_u32(Qh), uQl = smem_u32(Ql);
    const uint32_t uKh = smem_u32(Kh), uKl = smem_u32(Kl);
    const uint32_t uPh = smem_u32(Ph), uPl = smem_u32(Pl);

    const int tid = threadIdx.x;
    const int wid = tid >> 5, lane = tid & 31;
    const int wm = wid & 1, wn = wid >> 1;
    const int qt = blockIdx.x, h = blockIdx.y, b = blockIdx.z;
    const int q0 = qt * 32;
    const size_t headq = (size_t)b * L_ * 1024 + h * 64;

    // ---- load Q (pre-scaled, pre-split) ----
    #pragma unroll
    for (int t = 0; t < 2; t++) {
        int idx = tid + t * 256;
        int r = idx >> 4, c4 = (idx & 15) * 4;
        int l = q0 + r;
        ushort4 vh = make_ushort4(0,0,0,0), vl = make_ushort4(0,0,0,0);
        if (l < L_) {
            size_t go = headq + (size_t)l * 1024 + c4;
            vh = *reinterpret_cast<const ushort4*>(g_qh + go);
            vl = *reinterpret_cast<const ushort4*>(g_ql + go);
        }
        *reinterpret_cast<ushort4*>(Qh + r * QVST + c4) = vh;
        *reinterpret_cast<ushort4*>(Ql + r * QVST + c4) = vl;
    }

    // ---- phase 1: S = Q.K^T ----
    for (int kt = 0; kt < L_; kt += 128) {
        __syncthreads();
        #pragma unroll
        for (int t = 0; t < 8; t++) {
            int idx = tid + t * 256;
            int r = idx >> 4, c4 = (idx & 15) * 4;
            int l = kt + r;
            ushort4 vh = make_ushort4(0,0,0,0), vl = make_ushort4(0,0,0,0);
            if (l < L_) {
                size_t go = headq + (size_t)l * 1024 + c4;
                vh = *reinterpret_cast<const ushort4*>(g_kh + go);
                vl = *reinterpret_cast<const ushort4*>(g_kl + go);
            }
            *reinterpret_cast<ushort4*>(Kh + r * QVST + c4) = vh;
            *reinterpret_cast<ushort4*>(Kl + r * QVST + c4) = vl;
        }
        __syncthreads();

        float acc[4][4];
        #pragma unroll
        for (int i = 0; i < 4; i++)
            #pragma unroll
            for (int c = 0; c < 4; c++) acc[i][c] = 0.f;

        #pragma unroll
        for (int ks = 0; ks < 4; ks++) {
            uint32_t qh[4], ql[4], kh[2][4], kl[2][4];
            {
                int row = wm * 16 + (lane & 15);
                uint32_t off = (uint32_t)row * 144 + ks * 32 + ((lane >> 4) << 4);
                ldm4(qh, uQh + off);
                ldm4(ql, uQl + off);
            }
            #pragma unroll
            for (int p = 0; p < 2; p++) {
                int row = wn * 32 + p * 16 + (lane & 7) + ((lane >> 4) & 1) * 8;
                uint32_t off = (uint32_t)row * 144 + ks * 32 + (((lane >> 3) & 1) << 4);
                ldm4(kh[p], uKh + off);
                ldm4(kl[p], uKl + off);
            }
            #pragma unroll
            for (int nt = 0; nt < 4; nt++) {
                uint32_t* bh = &kh[nt >> 1][(nt & 1) * 2];
                uint32_t* bl = &kl[nt >> 1][(nt & 1) * 2];
                mma16816(acc[nt], qh, bh);
                mma16816(acc[nt], qh, bl);
                mma16816(acc[nt], ql, bh);
            }
        }

        int r0 = wm * 16 + (lane >> 2);
        #pragma unroll
        for (int nt = 0; nt < 4; nt++) {
            int col = kt + wn * 32 + nt * 8 + (lane & 3) * 2;
            if (col < L_)     S[r0 * SST + col]           = acc[nt][0];
            if (col + 1 < L_) S[r0 * SST + col + 1]       = acc[nt][1];
            if (col < L_)     S[(r0 + 8) * SST + col]     = acc[nt][2];
            if (col + 1 < L_) S[(r0 + 8) * SST + col + 1] = acc[nt][3];
        }
    }
    __syncthreads();

    // ---- softmax + attn write ----
    for (int r = wid * 4; r < wid * 4 + 4; r++) {
        int l = q0 + r;
        if (l >= L_) continue;
        float* Sr = S + r * SST;
        float m = -1e30f;
        for (int j = lane; j < L_; j += 32) m = fmaxf(m, Sr[j]);
        #pragma unroll
        for (int o = 16; o; o >>= 1) m = fmaxf(m, __shfl_xor_sync(0xffffffffu, m, o));
        float ssum = 0.f;
        for (int j = lane; j < L_; j += 32) { float e = __expf(Sr[j] - m); Sr[j] = e; ssum += e; }
        #pragma unroll
        for (int o = 16; o; o >>= 1) ssum += __shfl_xor_sync(0xffffffffu, ssum, o);
        float inv = 1.f / ssum;
        size_t abase = ((size_t)(b * H_ + h) * L_ + l) * L_;
        for (int j = lane; j < L_; j += 32) {
            float p = Sr[j] * inv;
            Sr[j] = p;
            if (attn_out) attn_out[abase + j] = p;
        }
    }

    // ---- phase 2: O = P.V ----
    float acc2[2][4];
    #pragma unroll
    for (int i = 0; i < 2; i++)
        #pragma unroll
        for (int c = 0; c < 4; c++) acc2[i][c] = 0.f;

    for (int kt = 0; kt < L_; kt += 128) {
        __syncthreads();
        #pragma unroll
        for (int t = 0; t < 8; t++) {
            int idx = tid + t * 256;
            int r = idx >> 4, c4 = (idx & 15) * 4;
            int l = kt + r;
            ushort4 vh = make_ushort4(0,0,0,0), vl = make_ushort4(0,0,0,0);
            if (l < L_) {
                size_t go = headq + (size_t)l * 1024 + c4;
                vh = *reinterpret_cast<const ushort4*>(g_vh + go);
                vl = *reinterpret_cast<const ushort4*>(g_vl + go);
            }
            *reinterpret_cast<ushort4*>(Kh + r * QVST + c4) = vh;
            *reinterpret_cast<ushort4*>(Kl + r * QVST + c4) = vl;
        }
        #pragma unroll
        for (int t = 0; t < 16; t++) {
            int idx = tid + t * 256;
            int r = idx >> 7, c = idx & 127;
            int col = kt + c;
            float p = (col < L_) ? S[r * SST + col] : 0.f;
            bf hh, ll;
            bsplit(p, &hh, &ll);
            Ph[r * PST + c] = hh;
            Pl[r * PST + c] = ll;
        }
        __syncthreads();

        #pragma unroll
        for (int ks = 0; ks < 8; ks++) {
            uint32_t ph[4], pl[4], vh[4], vl[4];
            {
                int row = wm * 16 + (lane & 15);
                uint32_t off = (uint32_t)row * 272 + ks * 32 + ((lane >> 4) << 4);
                ldm4(ph, uPh + off);
                ldm4(pl, uPl + off);
            }
            {
                int row = ks * 16 + (lane & 15);
                uint32_t off = (uint32_t)row * 144 + wn * 32 + ((lane >> 4) << 4);
                ldm4t(vh, uKh + off);
                ldm4t(vl, uKl + off);
            }
            #pragma unroll
            for (int nt = 0; nt < 2; nt++) {
                mma16816(acc2[nt], ph, &vh[nt * 2]);
                mma16816(acc2[nt], ph, &vl[nt * 2]);
                mma16816(acc2[nt], pl, &vh[nt * 2]);
            }
        }
    }

    // output -> split bf16 (FC GEMM input)
    #pragma unroll
    for (int half = 0; half < 2; half++) {
        int r = wm * 16 + (lane >> 2) + half * 8;
        int l = q0 + r;
        if (l >= L_) continue;
        #pragma unroll
        for (int nt = 0; nt < 2; nt++) {
            int d = wn * 16 + nt * 8 + (lane & 3) * 2;
            float vx = acc2[nt][half * 2 + 0];
            float vy = acc2[nt][half * 2 + 1];
            bf hx, lx, hy, ly;
            bsplit(vx, &hx, &lx);
            bsplit(vy, &hy, &ly);
            size_t go = headq + (size_t)l * 1024 + d;
            *reinterpret_cast<ushort2*>(g_aoh + go) = make_ushort2(
                __bfloat16_as_ushort(hx), __bfloat16_as_ushort(hy));
            *reinterpret_cast<ushort2*>(g_aol + go) = make_ushort2(
                __bfloat16_as_ushort(lx), __bfloat16_as_ushort(ly));
        }
    }
}

// =======================================================================
// launch
// =======================================================================
extern "C" void kernel_launch(void* const* d_in, const int* in_sizes, int n_in,
                              void* d_out, int out_size)
{
    const float* x    = (const float*)d_in[0];
    const float* wq0  = (const float*)d_in[1];
    const float* wq1  = (const float*)d_in[2];
    const float* wk0  = (const float*)d_in[3];
    const float* wk1  = (const float*)d_in[4];
    const float* wv0  = (const float*)d_in[5];
    const float* wv1  = (const float*)d_in[6];
    const float* fc_w = (const float*)d_in[7];
    const float* fc_b = (const float*)d_in[8];
    const float* ln_g = (const float*)d_in[9];
    const float* ln_b = (const float*)d_in[10];
    float* out = (float*)d_out;

    bf *p_xh, *p_xl, *p_qh, *p_ql, *p_kh, *p_kl, *p_vh, *p_vl, *p_aoh, *p_aol;
    bf *p_wth, *p_wtl;
    cudaGetSymbolAddress((void**)&p_xh,  g_xh);
    cudaGetSymbolAddress((void**)&p_xl,  g_xl);
    cudaGetSymbolAddress((void**)&p_qh,  g_qh);
    cudaGetSymbolAddress((void**)&p_ql,  g_ql);
    cudaGetSymbolAddress((void**)&p_kh,  g_kh);
    cudaGetSymbolAddress((void**)&p_kl,  g_kl);
    cudaGetSymbolAddress((void**)&p_vh,  g_vh);
    cudaGetSymbolAddress((void**)&p_vl,  g_vl);
    cudaGetSymbolAddress((void**)&p_aoh, g_aoh);
    cudaGetSymbolAddress((void**)&p_aol, g_aol);
    cudaGetSymbolAddress((void**)&p_wth, g_wth);
    cudaGetSymbolAddress((void**)&p_wtl, g_wtl);

    float* attn_ptr = ((size_t)out_size >= OUT_ELEMS + ATTN_ELEMS)
                        ? (out + OUT_ELEMS) : nullptr;

    cudaFuncSetAttribute(mma_gemm, cudaFuncAttributeMaxDynamicSharedMemorySize, 2 * STG_SZ);
    cudaFuncSetAttribute(attn_mma, cudaFuncAttributeMaxDynamicSharedMemorySize, ATTN_SMEM);

    // 1) LayerNorm (writes f32 + split bf16)
    ln_kernel<<<M_, 256>>>(x, ln_g, ln_b);

    // 2) transpose+split the 4 main weights
    dim3 tg(32, 32);
    tsplit_kernel<<<tg, 256>>>(wq0,  p_wth + 0 * (size_t)WSZ, p_wtl + 0 * (size_t)WSZ);
    tsplit_kernel<<<tg, 256>>>(wk0,  p_wth + 1 * (size_t)WSZ, p_wtl + 1 * (size_t)WSZ);
    tsplit_kernel<<<tg, 256>>>(wv0,  p_wth + 2 * (size_t)WSZ, p_wtl + 2 * (size_t)WSZ);
    tsplit_kernel<<<tg, 256>>>(fc_w, p_wth + 3 * (size_t)WSZ, p_wtl + 3 * (size_t)WSZ);

    // 3) fused QKV projections (split-bf16 epilogue, Q pre-scaled)
    dim3 gq(8, (M_ + 127) / 128, 3);
    mma_gemm<<<gq, 256, 2 * STG_SZ>>>(p_xh, p_xl, p_wth, p_wtl,
                                      nullptr, nullptr, nullptr,
                                      p_qh, p_ql, p_kh, p_kl, p_vh, p_vl, M_);

    // 4) exact fp32 fix for the 24 weight-set-1 rows
    seg_fix<<<dim3(24, 3), 256>>>(wq1, wk1, wv1);

    // 5) tensorized attention (writes attn + split-bf16 ao)
    attn_mma<<<dim3((L_ + 31) / 32, H_, B_), 256, ATTN_SMEM>>>(attn_ptr);

    // 6) FC (+bias+residual) -> out
    dim3 gf(8, (M_ + 127) / 128, 1);
    mma_gemm<<<gf, 256, 2 * STG_SZ>>>(p_aoh, p_aol, p_wth + 3 * (size_t)WSZ,
                                      p_wtl + 3 * (size_t)WSZ,
                                      out, fc_b, x,
                                      nullptr, nullptr, nullptr, nullptr, nullptr, nullptr, M_);
}

// round 9
// speedup vs baseline: 3.5748x; 1.4265x over previous
#include <cuda_runtime.h>
#include <cuda_bf16.h>
#include <cstdint>

#define B_ 8
#define L_ 1030
#define D_ 1024
#define H_ 16
#define M_ (B_*L_)          // 8240
#define WSZ (1024*1024)

typedef __nv_bfloat16 bf;

static const size_t OUT_ELEMS  = (size_t)M_ * D_;              // 8,437,760
static const size_t ATTN_ELEMS = (size_t)B_ * H_ * L_ * L_;    // 135,795,200

// Scratch (device globals)
__device__ float g_xn[M_*D_];               // exact LN output (seg_fix input)
__device__ bf g_xh[M_*D_], g_xl[M_*D_];     // split LN output (QKV GEMM A)
__device__ bf g_qh[M_*D_], g_ql[M_*D_];     // split Q (pre-scaled 0.125)
__device__ bf g_kh[M_*D_], g_kl[M_*D_];     // split K
__device__ bf g_vb[M_*D_];                  // single-bf16 V
__device__ bf g_aob[M_*D_];                 // single-bf16 attention output
__device__ bf g_wth[4*WSZ], g_wtl[4*WSZ];   // transposed weights [N][K] hi/lo

// =======================================================================
// helpers
// =======================================================================
static __device__ __forceinline__ uint32_t smem_u32(const void* p) {
    uint32_t a;
    asm("{ .reg .u64 t; cvta.to.shared.u64 t, %1; cvt.u32.u64 %0, t; }"
        : "=r"(a) : "l"(p));
    return a;
}
static __device__ __forceinline__ void ldm4(uint32_t* r, uint32_t addr) {
    asm volatile("ldmatrix.sync.aligned.m8n8.x4.shared.b16 {%0,%1,%2,%3}, [%4];"
        : "=r"(r[0]), "=r"(r[1]), "=r"(r[2]), "=r"(r[3]) : "r"(addr));
}
static __device__ __forceinline__ void ldm4t(uint32_t* r, uint32_t addr) {
    asm volatile("ldmatrix.sync.aligned.m8n8.x4.trans.shared.b16 {%0,%1,%2,%3}, [%4];"
        : "=r"(r[0]), "=r"(r[1]), "=r"(r[2]), "=r"(r[3]) : "r"(addr));
}
static __device__ __forceinline__ void mma16816(float* c, const uint32_t* a,
                                                const uint32_t* b) {
    asm volatile("mma.sync.aligned.m16n8k16.row.col.f32.bf16.bf16.f32 "
        "{%0,%1,%2,%3}, {%4,%5,%6,%7}, {%8,%9}, {%0,%1,%2,%3};"
        : "+f"(c[0]), "+f"(c[1]), "+f"(c[2]), "+f"(c[3])
        : "r"(a[0]), "r"(a[1]), "r"(a[2]), "r"(a[3]), "r"(b[0]), "r"(b[1]));
}
static __device__ __forceinline__ void bsplit(float v, bf* h, bf* l) {
    bf hh = __float2bfloat16_rn(v);
    *h = hh;
    *l = __float2bfloat16_rn(v - __bfloat162float(hh));
}
static __device__ __forceinline__ void cpa(uint32_t dst, const void* src, int sz) {
    asm volatile("cp.async.cg.shared.global [%0], [%1], 16, %2;"
                 :: "r"(dst), "l"(src), "r"(sz));
}
static __device__ __forceinline__ void cpa_commit() {
    asm volatile("cp.async.commit_group;");
}

// =======================================================================
// LayerNorm: writes exact f32 xn AND split bf16 (xh, xl)
// =======================================================================
__global__ void __launch_bounds__(256) ln_kernel(const float* __restrict__ x,
                                                 const float* __restrict__ gam,
                                                 const float* __restrict__ bet)
{
    int row = blockIdx.x;
    int t = threadIdx.x;
    const float4* xr = reinterpret_cast<const float4*>(x + (size_t)row * D_);
    float4 v = xr[t];
    float s  = v.x + v.y + v.z + v.w;
    float ss = v.x*v.x + v.y*v.y + v.z*v.z + v.w*v.w;
    __shared__ float rs[8], rss[8], stat[2];
    #pragma unroll
    for (int o = 16; o; o >>= 1) {
        s  += __shfl_xor_sync(0xffffffffu, s,  o);
        ss += __shfl_xor_sync(0xffffffffu, ss, o);
    }
    if ((t & 31) == 0) { rs[t >> 5] = s; rss[t >> 5] = ss; }
    __syncthreads();
    if (t == 0) {
        float S = 0.f, SS = 0.f;
        #pragma unroll
        for (int i = 0; i < 8; i++) { S += rs[i]; SS += rss[i]; }
        float mu  = S / (float)D_;
        float var = SS / (float)D_ - mu * mu;
        stat[0] = mu;
        stat[1] = rsqrtf(var + 1e-6f);
    }
    __syncthreads();
    float mu = stat[0], inv = stat[1];
    float4 g4 = reinterpret_cast<const float4*>(gam)[t];
    float4 b4 = reinterpret_cast<const float4*>(bet)[t];
    float4 o;
    o.x = (v.x - mu) * inv * g4.x + b4.x;
    o.y = (v.y - mu) * inv * g4.y + b4.y;
    o.z = (v.z - mu) * inv * g4.z + b4.z;
    o.w = (v.w - mu) * inv * g4.w + b4.w;
    size_t base = (size_t)row * D_ + t * 4;
    *reinterpret_cast<float4*>(g_xn + base) = o;
    bf h[4], l[4];
    bsplit(o.x, &h[0], &l[0]); bsplit(o.y, &h[1], &l[1]);
    bsplit(o.z, &h[2], &l[2]); bsplit(o.w, &h[3], &l[3]);
    *reinterpret_cast<ushort4*>(g_xh + base) = make_ushort4(
        __bfloat16_as_ushort(h[0]), __bfloat16_as_ushort(h[1]),
        __bfloat16_as_ushort(h[2]), __bfloat16_as_ushort(h[3]));
    *reinterpret_cast<ushort4*>(g_xl + base) = make_ushort4(
        __bfloat16_as_ushort(l[0]), __bfloat16_as_ushort(l[1]),
        __bfloat16_as_ushort(l[2]), __bfloat16_as_ushort(l[3]));
}

// =======================================================================
// transpose + split: W[1024(K),1024(N)] -> Wt[N][K] bf16 hi/lo
// =======================================================================
__global__ void __launch_bounds__(256) tsplit_kernel(const float* __restrict__ W,
                                                     bf* __restrict__ th,
                                                     bf* __restrict__ tl)
{
    __shared__ float sm[32][33];
    int c0 = blockIdx.x * 32, r0 = blockIdx.y * 32;
    int tx = threadIdx.x & 31, ty = threadIdx.x >> 5;
    #pragma unroll
    for (int k = 0; k < 32; k += 8)
        sm[ty + k][tx] = W[(size_t)(r0 + ty + k) * 1024 + c0 + tx];
    __syncthreads();
    #pragma unroll
    for (int k = 0; k < 32; k += 8) {
        float v = sm[tx][ty + k];
        int n = c0 + ty + k, kk = r0 + tx;
        bf h, l;
        bsplit(v, &h, &l);
        th[(size_t)n * 1024 + kk] = h;
        tl[(size_t)n * 1024 + kk] = l;
    }
}

// =======================================================================
// HMMA GEMM, cp.async double-buffered, BK=32, mixed terms.
// Tile 128x128, 8 warps (4M x 2N), warp tile 32x64.
// terms=3 (split A+B, 3 MMAs) for Q/K; terms=1 for V / FC.
// Epilogue: f32(+bias+resid) if Cf; split hi/lo if Ol; else single bf16.
// =======================================================================
#define STG_SZ 40960
__global__ void __launch_bounds__(256) mma_gemm(
    const bf* __restrict__ Ah, const bf* __restrict__ Al,
    const bf* __restrict__ Bh_, const bf* __restrict__ Bl_,
    float* __restrict__ Cf, const float* __restrict__ bias,
    const float* __restrict__ resid,
    bf* Q_h, bf* Q_l, bf* K_h, bf* K_l, bf* V_b, int M)
{
    extern __shared__ char smem[];
    const uint32_t sb = smem_u32(smem);

    const int tid = threadIdx.x;
    const int wid = tid >> 5, lane = tid & 31;
    const int wm = wid & 3, wn = wid >> 2;
    const int m0 = blockIdx.y * 128, n0 = blockIdx.x * 128;
    const int z = blockIdx.z;

    const bf* Bh = Bh_ + (size_t)z * WSZ;
    const bf* Bl = Bl_ ? (Bl_ + (size_t)z * WSZ) : nullptr;
    const int terms = (Cf || z == 2) ? 1 : 3;
    bf* Oh = (z == 0) ? Q_h : (z == 1) ? K_h : V_b;
    bf* Ol = (z == 0) ? Q_l : (z == 1) ? K_l : nullptr;
    const float scale = (z == 0) ? 0.125f : 1.0f;

    float acc[2][8][4];
    #pragma unroll
    for (int i = 0; i < 2; i++)
        #pragma unroll
        for (int j = 0; j < 8; j++)
            #pragma unroll
            for (int c = 0; c < 4; c++) acc[i][j][c] = 0.f;

    const int lr = tid >> 2;            // 0..63
    const int lc = (tid & 3) * 16;      // byte col within 64B row

    auto prefetch = [&](int kt, int stg) {
        uint32_t base = sb + stg * STG_SZ;
        #pragma unroll
        for (int t = 0; t < 2; t++) {
            int r = lr + t * 64;
            uint32_t so = (uint32_t)r * 80 + lc;
            int arow = m0 + r;
            int szA = (arow < M) ? 16 : 0;
            int ar = (arow < M) ? arow : 0;
            cpa(base + so, (const char*)(Ah + (size_t)ar * 1024 + kt) + lc, szA);
            cpa(base + 20480 + so, (const char*)(Bh + (size_t)(n0 + r) * 1024 + kt) + lc, 16);
            if (terms == 3) {
                cpa(base + 10240 + so, (const char*)(Al + (size_t)ar * 1024 + kt) + lc, szA);
                cpa(base + 30720 + so, (const char*)(Bl + (size_t)(n0 + r) * 1024 + kt) + lc, 16);
            }
        }
        cpa_commit();
    };

    prefetch(0, 0);

    for (int it = 0; it < 32; it++) {
        if (it + 1 < 32) {
            prefetch((it + 1) * 32, (it + 1) & 1);
            asm volatile("cp.async.wait_group 1;");
        } else {
            asm volatile("cp.async.wait_group 0;");
        }
        __syncthreads();

        uint32_t st = sb + (it & 1) * STG_SZ;
        uint32_t sAh = st, sAl = st + 10240, sBh = st + 20480, sBl = st + 30720;

        #pragma unroll
        for (int ks = 0; ks < 2; ks++) {
            uint32_t a_h[2][4], a_l[2][4], b_h[4][4], b_l[4][4];
            #pragma unroll
            for (int mt = 0; mt < 2; mt++) {
                int row = wm * 32 + mt * 16 + (lane & 15);
                uint32_t off = (uint32_t)row * 80 + ks * 32 + ((lane >> 4) << 4);
                ldm4(a_h[mt], sAh + off);
                if (terms == 3) ldm4(a_l[mt], sAl + off);
            }
            #pragma unroll
            for (int p = 0; p < 4; p++) {
                int row = wn * 64 + p * 16 + (lane & 7) + ((lane >> 4) & 1) * 8;
                uint32_t off = (uint32_t)row * 80 + ks * 32 + (((lane >> 3) & 1) << 4);
                ldm4(b_h[p], sBh + off);
                if (terms == 3) ldm4(b_l[p], sBl + off);
            }
            #pragma unroll
            for (int mt = 0; mt < 2; mt++)
                #pragma unroll
                for (int nt = 0; nt < 8; nt++) {
                    uint32_t* bh = &b_h[nt >> 1][(nt & 1) * 2];
                    mma16816(acc[mt][nt], a_h[mt], bh);
                    if (terms == 3) {
                        uint32_t* bl = &b_l[nt >> 1][(nt & 1) * 2];
                        mma16816(acc[mt][nt], a_h[mt], bl);
                        mma16816(acc[mt][nt], a_l[mt], bh);
                    }
                }
        }
        __syncthreads();
    }

    // epilogue
    #pragma unroll
    for (int mt = 0; mt < 2; mt++) {
        #pragma unroll
        for (int half = 0; half < 2; half++) {
            int row = m0 + wm * 32 + mt * 16 + (lane >> 2) + half * 8;
            if (row >= M) continue;
            #pragma unroll
            for (int nt = 0; nt < 8; nt++) {
                int col = n0 + wn * 64 + nt * 8 + (lane & 3) * 2;
                float vx = acc[mt][nt][half * 2 + 0];
                float vy = acc[mt][nt][half * 2 + 1];
                size_t go = (size_t)row * 1024 + col;
                if (Cf) {
                    if (bias) { vx += bias[col]; vy += bias[col + 1]; }
                    float2 v2; v2.x = vx; v2.y = vy;
                    if (resid) {
                        float2 rv = *reinterpret_cast<const float2*>(resid + go);
                        v2.x += rv.x; v2.y += rv.y;
                    }
                    *reinterpret_cast<float2*>(Cf + go) = v2;
                } else if (Ol) {
                    vx *= scale; vy *= scale;
                    bf hx, lx, hy, ly;
                    bsplit(vx, &hx, &lx);
                    bsplit(vy, &hy, &ly);
                    *reinterpret_cast<ushort2*>(Oh + go) = make_ushort2(
                        __bfloat16_as_ushort(hx), __bfloat16_as_ushort(hy));
                    *reinterpret_cast<ushort2*>(Ol + go) = make_ushort2(
                        __bfloat16_as_ushort(lx), __bfloat16_as_ushort(ly));
                } else {
                    *reinterpret_cast<ushort2*>(Oh + go) = make_ushort2(
                        __bfloat16_as_ushort(__float2bfloat16_rn(vx)),
                        __bfloat16_as_ushort(__float2bfloat16_rn(vy)));
                }
            }
        }
    }
}

// =======================================================================
// segment fix-up: rows l in [1027,1030) use weight set 1 (exact fp32)
// =======================================================================
__global__ void __launch_bounds__(256) seg_fix(const float* __restrict__ wq1,
                                               const float* __restrict__ wk1,
                                               const float* __restrict__ wv1)
{
    int which = blockIdx.y;
    const float* W = (which == 0) ? wq1 : (which == 1) ? wk1 : wv1;
    float scale = (which == 0) ? 0.125f : 1.0f;
    int batch = blockIdx.x / 3, s = blockIdx.x % 3;
    int row = batch * L_ + (L_ - 3) + s;

    __shared__ float xs[1024];
    for (int i = threadIdx.x; i < 1024; i += 256) xs[i] = g_xn[(size_t)row * 1024 + i];
    __syncthreads();

    float a[4] = {0.f, 0.f, 0.f, 0.f};
    const float* Wc = W + threadIdx.x;
    for (int k = 0; k < 1024; k++) {
        float xv = xs[k];
        const float* wr = Wc + (size_t)k * 1024;
        a[0] += xv * wr[0];
        a[1] += xv * wr[256];
        a[2] += xv * wr[512];
        a[3] += xv * wr[768];
    }
    #pragma unroll
    for (int j = 0; j < 4; j++) {
        float v = a[j] * scale;
        size_t off = (size_t)row * 1024 + threadIdx.x + j * 256;
        if (which == 2) {
            g_vb[off] = __float2bfloat16_rn(v);
        } else {
            bf h, l;
            bsplit(v, &h, &l);
            if (which == 0) { g_qh[off] = h; g_ql[off] = l; }
            else            { g_kh[off] = h; g_kl[off] = l; }
        }
    }
}

// =======================================================================
// tensorized fused attention: 3-term S = Q.K^T, single-bf16 P.V
// block = (qt, h, b): 32 query rows, 256 threads (8 warps, 2M x 4N)
// smem: S 32x1032 f32 | Qh/Ql 32x72 | KV 2 stages (hi 128x72 + lo 128x72) | Pb 32x136
// =======================================================================
#define SST 1032
#define OFF_Q  132096
#define OFF_KV 141312
#define KVSTG2 36864
#define OFF_P  215040
#define ATTN_SMEM 223744
#define NTILE 9

__global__ void __launch_bounds__(256) attn_mma(float* __restrict__ attn_out)
{
    extern __shared__ char sm[];
    float* S = reinterpret_cast<float*>(sm);
    bf* Qh = reinterpret_cast<bf*>(sm + OFF_Q);
    bf* Ql = Qh + 32 * 72;
    bf* Pb = reinterpret_cast<bf*>(sm + OFF_P);
    const uint32_t uQh = smem_u32(Qh), uQl = smem_u32(Ql);
    const uint32_t uKV = smem_u32(sm + OFF_KV);
    const uint32_t uP = smem_u32(Pb);

    const int tid = threadIdx.x;
    const int wid = tid >> 5, lane = tid & 31;
    const int wm = wid & 1, wn = wid >> 1;      // 2 (M) x 4 (N)
    const int qt = blockIdx.x, h = blockIdx.y, b = blockIdx.z;
    const int q0 = qt * 32;
    const size_t headq = (size_t)b * L_ * 1024 + h * 64;

    // K tile prefetch: hi + lo (128 rows x 64 bf16 each)
    auto prefetch_k = [&](int kt, int stg) {
        uint32_t base = uKV + stg * KVSTG2;
        #pragma unroll
        for (int t = 0; t < 4; t++) {
            int idx = tid + t * 256;          // 0..1023
            int r = idx >> 3;
            int cb = (idx & 7) * 16;
            int l = kt + r;
            int sz = (l < L_) ? 16 : 0;
            int lr2 = (l < L_) ? l : 0;
            size_t go = headq + (size_t)lr2 * 1024;
            cpa(base + (uint32_t)r * 144 + cb,         (const char*)(g_kh + go) + cb, sz);
            cpa(base + 18432 + (uint32_t)r * 144 + cb, (const char*)(g_kl + go) + cb, sz);
        }
        cpa_commit();
    };
    // V tile prefetch: single bf16 (hi region only)
    auto prefetch_v = [&](int kt, int stg) {
        uint32_t base = uKV + stg * KVSTG2;
        #pragma unroll
        for (int t = 0; t < 4; t++) {
            int idx = tid + t * 256;
            int r = idx >> 3;
            int cb = (idx & 7) * 16;
            int l = kt + r;
            int sz = (l < L_) ? 16 : 0;
            int lr2 = (l < L_) ? l : 0;
            cpa(base + (uint32_t)r * 144 + cb,
                (const char*)(g_vb + headq + (size_t)lr2 * 1024) + cb, sz);
        }
        cpa_commit();
    };

    prefetch_k(0, 0);

    // ---- load Q hi/lo ----
    #pragma unroll
    for (int t = 0; t < 2; t++) {
        int idx = tid + t * 256;
        int r = idx >> 4, c4 = (idx & 15) * 4;
        int l = q0 + r;
        ushort4 vh = make_ushort4(0,0,0,0), vl = make_ushort4(0,0,0,0);
        if (l < L_) {
            size_t go = headq + (size_t)l * 1024 + c4;
            vh = *reinterpret_cast<const ushort4*>(g_qh + go);
            vl = *reinterpret_cast<const ushort4*>(g_ql + go);
        }
        *reinterpret_cast<ushort4*>(Qh + r * 72 + c4) = vh;
        *reinterpret_cast<ushort4*>(Ql + r * 72 + c4) = vl;
    }

    // ---- phase 1: S = Q.K^T (3-term) ----
    for (int t9 = 0; t9 < NTILE; t9++) {
        if (t9 + 1 < NTILE) {
            prefetch_k((t9 + 1) * 128, (t9 + 1) & 1);
            asm volatile("cp.async.wait_group 1;");
        } else {
            asm volatile("cp.async.wait_group 0;");
        }
        __syncthreads();
        uint32_t uKh = uKV + (t9 & 1) * KVSTG2;
        uint32_t uKl = uKh + 18432;
        int kt = t9 * 128;

        float acc[4][4];
        #pragma unroll
        for (int i = 0; i < 4; i++)
            #pragma unroll
            for (int c = 0; c < 4; c++) acc[i][c] = 0.f;

        #pragma unroll
        for (int ks = 0; ks < 4; ks++) {
            uint32_t qh[4], ql[4], kh[2][4], kl[2][4];
            {
                int row = wm * 16 + (lane & 15);
                uint32_t off = (uint32_t)row * 144 + ks * 32 + ((lane >> 4) << 4);
                ldm4(qh, uQh + off);
                ldm4(ql, uQl + off);
            }
            #pragma unroll
            for (int p = 0; p < 2; p++) {
                int row = wn * 32 + p * 16 + (lane & 7) + ((lane >> 4) & 1) * 8;
                uint32_t off = (uint32_t)row * 144 + ks * 32 + (((lane >> 3) & 1) << 4);
                ldm4(kh[p], uKh + off);
                ldm4(kl[p], uKl + off);
            }
            #pragma unroll
            for (int nt = 0; nt < 4; nt++) {
                uint32_t* bh = &kh[nt >> 1][(nt & 1) * 2];
                uint32_t* bl = &kl[nt >> 1][(nt & 1) * 2];
                mma16816(acc[nt], qh, bh);
                mma16816(acc[nt], qh, bl);
                mma16816(acc[nt], ql, bh);
            }
        }

        int r0 = wm * 16 + (lane >> 2);
        #pragma unroll
        for (int nt = 0; nt < 4; nt++) {
            int col = kt + wn * 32 + nt * 8 + (lane & 3) * 2;
            if (col < L_)     S[r0 * SST + col]           = acc[nt][0];
            if (col + 1 < L_) S[r0 * SST + col + 1]       = acc[nt][1];
            if (col < L_)     S[(r0 + 8) * SST + col]     = acc[nt][2];
            if (col + 1 < L_) S[(r0 + 8) * SST + col + 1] = acc[nt][3];
        }
        __syncthreads();
    }

    // overlap: start V tile 0 load during softmax
    prefetch_v(0, 0);

    // ---- softmax + attn write (warp per 4 rows) ----
    for (int r = wid * 4; r < wid * 4 + 4; r++) {
        int l = q0 + r;
        if (l >= L_) continue;
        float* Sr = S + r * SST;
        float m = -1e30f;
        for (int j = lane; j < L_; j += 32) m = fmaxf(m, Sr[j]);
        #pragma unroll
        for (int o = 16; o; o >>= 1) m = fmaxf(m, __shfl_xor_sync(0xffffffffu, m, o));
        float ssum = 0.f;
        for (int j = lane; j < L_; j += 32) { float e = __expf(Sr[j] - m); Sr[j] = e; ssum += e; }
        #pragma unroll
        for (int o = 16; o; o >>= 1) ssum += __shfl_xor_sync(0xffffffffu, ssum, o);
        float inv = 1.f / ssum;
        size_t abase = ((size_t)(b * H_ + h) * L_ + l) * L_;
        for (int j = lane; j < L_; j += 32) {
            float p = Sr[j] * inv;
            Sr[j] = p;
            if (attn_out) attn_out[abase + j] = p;
        }
    }
    __syncthreads();

    // ---- phase 2: O = P.V (single bf16) ----
    float acc2[2][4];
    #pragma unroll
    for (int i = 0; i < 2; i++)
        #pragma unroll
        for (int c = 0; c < 4; c++) acc2[i][c] = 0.f;

    for (int t9 = 0; t9 < NTILE; t9++) {
        if (t9 + 1 < NTILE) prefetch_v((t9 + 1) * 128, (t9 + 1) & 1);
        int kt = t9 * 128;
        // convert P tile -> bf16 (overlaps the V load)
        #pragma unroll
        for (int t = 0; t < 16; t++) {
            int idx = tid + t * 256;          // 0..4095
            int r = idx >> 7, c = idx & 127;
            int col = kt + c;
            float p = (col < L_) ? S[r * SST + col] : 0.f;
            Pb[r * 136 + c] = __float2bfloat16_rn(p);
        }
        if (t9 + 1 < NTILE) asm volatile("cp.async.wait_group 1;");
        else                asm volatile("cp.async.wait_group 0;");
        __syncthreads();
        uint32_t uV = uKV + (t9 & 1) * KVSTG2;

        #pragma unroll
        for (int ks = 0; ks < 8; ks++) {
            uint32_t p_[4], v_[4];
            {
                int row = wm * 16 + (lane & 15);
                uint32_t off = (uint32_t)row * 272 + ks * 32 + ((lane >> 4) << 4);
                ldm4(p_, uP + off);
            }
            {
                int row = ks * 16 + (lane & 15);
                uint32_t off = (uint32_t)row * 144 + wn * 32 + ((lane >> 4) << 4);
                ldm4t(v_, uV + off);
            }
            #pragma unroll
            for (int nt = 0; nt < 2; nt++)
                mma16816(acc2[nt], p_, &v_[nt * 2]);
        }
        __syncthreads();
    }

    // output -> bf16 (FC GEMM input)
    #pragma unroll
    for (int half = 0; half < 2; half++) {
        int r = wm * 16 + (lane >> 2) + half * 8;
        int l = q0 + r;
        if (l >= L_) continue;
        #pragma unroll
        for (int nt = 0; nt < 2; nt++) {
            int d = wn * 16 + nt * 8 + (lane & 3) * 2;
            size_t go = headq + (size_t)l * 1024 + d;
            *reinterpret_cast<ushort2*>(g_aob + go) = make_ushort2(
                __bfloat16_as_ushort(__float2bfloat16_rn(acc2[nt][half * 2 + 0])),
                __bfloat16_as_ushort(__float2bfloat16_rn(acc2[nt][half * 2 + 1])));
        }
    }
}

// =======================================================================
// launch
// =======================================================================
extern "C" void kernel_launch(void* const* d_in, const int* in_sizes, int n_in,
                              void* d_out, int out_size)
{
    const float* x    = (const float*)d_in[0];
    const float* wq0  = (const float*)d_in[1];
    const float* wq1  = (const float*)d_in[2];
    const float* wk0  = (const float*)d_in[3];
    const float* wk1  = (const float*)d_in[4];
    const float* wv0  = (const float*)d_in[5];
    const float* wv1  = (const float*)d_in[6];
    const float* fc_w = (const float*)d_in[7];
    const float* fc_b = (const float*)d_in[8];
    const float* ln_g = (const float*)d_in[9];
    const float* ln_b = (const float*)d_in[10];
    float* out = (float*)d_out;

    bf *p_xh, *p_xl, *p_qh, *p_ql, *p_kh, *p_kl, *p_vb, *p_aob, *p_wth, *p_wtl;
    cudaGetSymbolAddress((void**)&p_xh,  g_xh);
    cudaGetSymbolAddress((void**)&p_xl,  g_xl);
    cudaGetSymbolAddress((void**)&p_qh,  g_qh);
    cudaGetSymbolAddress((void**)&p_ql,  g_ql);
    cudaGetSymbolAddress((void**)&p_kh,  g_kh);
    cudaGetSymbolAddress((void**)&p_kl,  g_kl);
    cudaGetSymbolAddress((void**)&p_vb,  g_vb);
    cudaGetSymbolAddress((void**)&p_aob, g_aob);
    cudaGetSymbolAddress((void**)&p_wth, g_wth);
    cudaGetSymbolAddress((void**)&p_wtl, g_wtl);

    float* attn_ptr = ((size_t)out_size >= OUT_ELEMS + ATTN_ELEMS)
                        ? (out + OUT_ELEMS) : nullptr;

    cudaFuncSetAttribute(mma_gemm, cudaFuncAttributeMaxDynamicSharedMemorySize, 2 * STG_SZ);
    cudaFuncSetAttribute(attn_mma, cudaFuncAttributeMaxDynamicSharedMemorySize, ATTN_SMEM);

    // 1) LayerNorm (f32 + split bf16)
    ln_kernel<<<M_, 256>>>(x, ln_g, ln_b);

    // 2) transpose+split the 4 main weights (V/FC use hi only)
    dim3 tg(32, 32);
    tsplit_kernel<<<tg, 256>>>(wq0,  p_wth + 0 * (size_t)WSZ, p_wtl + 0 * (size_t)WSZ);
    tsplit_kernel<<<tg, 256>>>(wk0,  p_wth + 1 * (size_t)WSZ, p_wtl + 1 * (size_t)WSZ);
    tsplit_kernel<<<tg, 256>>>(wv0,  p_wth + 2 * (size_t)WSZ, p_wtl + 2 * (size_t)WSZ);
    tsplit_kernel<<<tg, 256>>>(fc_w, p_wth + 3 * (size_t)WSZ, p_wtl + 3 * (size_t)WSZ);

    // 3) fused QKV projections (Q/K 3-term split epilogue, V single)
    dim3 gq(8, (M_ + 127) / 128, 3);
    mma_gemm<<<gq, 256, 2 * STG_SZ>>>(p_xh, p_xl, p_wth, p_wtl,
                                      nullptr, nullptr, nullptr,
                                      p_qh, p_ql, p_kh, p_kl, p_vb, M_);

    // 4) exact fp32 fix for the 24 weight-set-1 rows
    seg_fix<<<dim3(24, 3), 256>>>(wq1, wk1, wv1);

    // 5) tensorized attention (3-term S, single P.V)
    attn_mma<<<dim3((L_ + 31) / 32, H_, B_), 256, ATTN_SMEM>>>(attn_ptr);

    // 6) FC (+bias+residual) -> out, single-term
    dim3 gf(8, (M_ + 127) / 128, 1);
    mma_gemm<<<gf, 256, 2 * STG_SZ>>>(p_aob, nullptr,
                                      p_wth + 3 * (size_t)WSZ, nullptr,
                                      out, fc_b, x,
                                      nullptr, nullptr, nullptr, nullptr, nullptr, M_);
}

// round 10
// speedup vs baseline: 5.2533x; 1.4695x over previous
#include <cuda_runtime.h>
#include <cuda_fp16.h>
#include <cstdint>

#define B_ 8
#define L_ 1030
#define D_ 1024
#define H_ 16
#define M_ (B_*L_)          // 8240
#define WSZ (1024*1024)

typedef __half hf;

static const size_t OUT_ELEMS  = (size_t)M_ * D_;              // 8,437,760
static const size_t ATTN_ELEMS = (size_t)B_ * H_ * L_ * L_;    // 135,795,200

// Scratch (device globals)
__device__ float g_xn[M_*D_];               // exact LN output (seg_fix input)
__device__ hf g_xb[M_*D_];                  // fp16 LN output (GEMM A)
__device__ hf g_qb[M_*D_];                  // fp16 Q (pre-scaled 0.125)
__device__ hf g_kb[M_*D_];
__device__ hf g_vb[M_*D_];
__device__ hf g_aob[M_*D_];                 // fp16 attention output
__device__ hf g_wt[4*WSZ];                  // transposed fp16 weights [N][K]

// =======================================================================
// helpers
// =======================================================================
static __device__ __forceinline__ uint32_t smem_u32(const void* p) {
    uint32_t a;
    asm("{ .reg .u64 t; cvta.to.shared.u64 t, %1; cvt.u32.u64 %0, t; }"
        : "=r"(a) : "l"(p));
    return a;
}
static __device__ __forceinline__ void ldm4(uint32_t* r, uint32_t addr) {
    asm volatile("ldmatrix.sync.aligned.m8n8.x4.shared.b16 {%0,%1,%2,%3}, [%4];"
        : "=r"(r[0]), "=r"(r[1]), "=r"(r[2]), "=r"(r[3]) : "r"(addr));
}
static __device__ __forceinline__ void ldm4t(uint32_t* r, uint32_t addr) {
    asm volatile("ldmatrix.sync.aligned.m8n8.x4.trans.shared.b16 {%0,%1,%2,%3}, [%4];"
        : "=r"(r[0]), "=r"(r[1]), "=r"(r[2]), "=r"(r[3]) : "r"(addr));
}
static __device__ __forceinline__ void mma16816(float* c, const uint32_t* a,
                                                const uint32_t* b) {
    asm volatile("mma.sync.aligned.m16n8k16.row.col.f32.f16.f16.f32 "
        "{%0,%1,%2,%3}, {%4,%5,%6,%7}, {%8,%9}, {%0,%1,%2,%3};"
        : "+f"(c[0]), "+f"(c[1]), "+f"(c[2]), "+f"(c[3])
        : "r"(a[0]), "r"(a[1]), "r"(a[2]), "r"(a[3]), "r"(b[0]), "r"(b[1]));
}
static __device__ __forceinline__ void cpa(uint32_t dst, const void* src, int sz) {
    asm volatile("cp.async.cg.shared.global [%0], [%1], 16, %2;"
                 :: "r"(dst), "l"(src), "r"(sz));
}
static __device__ __forceinline__ void cpa_commit() {
    asm volatile("cp.async.commit_group;");
}
static __device__ __forceinline__ unsigned short h2u(hf v) {
    return __half_as_ushort(v);
}

// =======================================================================
// LayerNorm: writes exact f32 xn AND fp16 xb
// =======================================================================
__global__ void __launch_bounds__(256) ln_kernel(const float* __restrict__ x,
                                                 const float* __restrict__ gam,
                                                 const float* __restrict__ bet)
{
    int row = blockIdx.x;
    int t = threadIdx.x;
    const float4* xr = reinterpret_cast<const float4*>(x + (size_t)row * D_);
    float4 v = xr[t];
    float s  = v.x + v.y + v.z + v.w;
    float ss = v.x*v.x + v.y*v.y + v.z*v.z + v.w*v.w;
    __shared__ float rs[8], rss[8], stat[2];
    #pragma unroll
    for (int o = 16; o; o >>= 1) {
        s  += __shfl_xor_sync(0xffffffffu, s,  o);
        ss += __shfl_xor_sync(0xffffffffu, ss, o);
    }
    if ((t & 31) == 0) { rs[t >> 5] = s; rss[t >> 5] = ss; }
    __syncthreads();
    if (t == 0) {
        float S = 0.f, SS = 0.f;
        #pragma unroll
        for (int i = 0; i < 8; i++) { S += rs[i]; SS += rss[i]; }
        float mu  = S / (float)D_;
        float var = SS / (float)D_ - mu * mu;
        stat[0] = mu;
        stat[1] = rsqrtf(var + 1e-6f);
    }
    __syncthreads();
    float mu = stat[0], inv = stat[1];
    float4 g4 = reinterpret_cast<const float4*>(gam)[t];
    float4 b4 = reinterpret_cast<const float4*>(bet)[t];
    float4 o;
    o.x = (v.x - mu) * inv * g4.x + b4.x;
    o.y = (v.y - mu) * inv * g4.y + b4.y;
    o.z = (v.z - mu) * inv * g4.z + b4.z;
    o.w = (v.w - mu) * inv * g4.w + b4.w;
    size_t base = (size_t)row * D_ + t * 4;
    *reinterpret_cast<float4*>(g_xn + base) = o;
    *reinterpret_cast<ushort4*>(g_xb + base) = make_ushort4(
        h2u(__float2half_rn(o.x)), h2u(__float2half_rn(o.y)),
        h2u(__float2half_rn(o.z)), h2u(__float2half_rn(o.w)));
}

// =======================================================================
// transpose + convert: W[1024(K),1024(N)] row-major -> Wt[N][K] fp16
// =======================================================================
__global__ void __launch_bounds__(256) tconv_kernel(const float* __restrict__ W,
                                                    hf* __restrict__ tw)
{
    __shared__ float sm[32][33];
    int c0 = blockIdx.x * 32, r0 = blockIdx.y * 32;
    int tx = threadIdx.x & 31, ty = threadIdx.x >> 5;
    #pragma unroll
    for (int k = 0; k < 32; k += 8)
        sm[ty + k][tx] = W[(size_t)(r0 + ty + k) * 1024 + c0 + tx];
    __syncthreads();
    #pragma unroll
    for (int k = 0; k < 32; k += 8) {
        float v = sm[tx][ty + k];
        int n = c0 + ty + k, kk = r0 + tx;
        tw[(size_t)n * 1024 + kk] = __float2half_rn(v);
    }
}

// =======================================================================
// single-fp16 HMMA GEMM, cp.async double-buffered, BK=64.
// Tile 128x128, 8 warps (4 M x 2 N), warp tile 32x64.
// smem per stage: A 128x72 + B 128x72 fp16 = 36864 B; 2 stages.
// =======================================================================
#define GSTG 36864
__global__ void __launch_bounds__(256) mma_gemm(
    const hf* __restrict__ A, const hf* __restrict__ Bw_,
    float* __restrict__ Cf, const float* __restrict__ bias,
    const float* __restrict__ resid,
    hf* Q_b, hf* K_b, hf* V_b, int M)
{
    extern __shared__ char smem[];
    const uint32_t sb = smem_u32(smem);

    const int tid = threadIdx.x;
    const int wid = tid >> 5, lane = tid & 31;
    const int wm = wid & 3, wn = wid >> 2;
    const int m0 = blockIdx.y * 128, n0 = blockIdx.x * 128;
    const int z = blockIdx.z;

    const hf* Bw = Bw_ + (size_t)z * WSZ;
    hf* Ob = (z == 0) ? Q_b : (z == 1) ? K_b : V_b;
    const float scale = (z == 0) ? 0.125f : 1.0f;

    float acc[2][8][4];
    #pragma unroll
    for (int i = 0; i < 2; i++)
        #pragma unroll
        for (int j = 0; j < 8; j++)
            #pragma unroll
            for (int c = 0; c < 4; c++) acc[i][j][c] = 0.f;

    auto prefetch = [&](int kt, int stg) {
        uint32_t base = sb + stg * GSTG;
        #pragma unroll
        for (int t = 0; t < 4; t++) {
            int idx = tid + t * 256;          // 0..1023
            int r = idx >> 3;
            int cb = (idx & 7) * 16;          // byte col (0..112)
            uint32_t so = (uint32_t)r * 144 + cb;
            int arow = m0 + r;
            int sz = (arow < M) ? 16 : 0;
            int ar = (arow < M) ? arow : 0;
            cpa(base + so, (const char*)(A + (size_t)ar * 1024 + kt) + cb, sz);
            cpa(base + 18432 + so, (const char*)(Bw + (size_t)(n0 + r) * 1024 + kt) + cb, 16);
        }
        cpa_commit();
    };

    prefetch(0, 0);

    for (int it = 0; it < 16; it++) {
        if (it + 1 < 16) {
            prefetch((it + 1) * 64, (it + 1) & 1);
            asm volatile("cp.async.wait_group 1;");
        } else {
            asm volatile("cp.async.wait_group 0;");
        }
        __syncthreads();

        uint32_t st = sb + (it & 1) * GSTG;
        uint32_t sA = st, sB = st + 18432;

        #pragma unroll
        for (int ks = 0; ks < 4; ks++) {
            uint32_t a_[2][4], b_[4][4];
            #pragma unroll
            for (int mt = 0; mt < 2; mt++) {
                int row = wm * 32 + mt * 16 + (lane & 15);
                uint32_t off = (uint32_t)row * 144 + ks * 32 + ((lane >> 4) << 4);
                ldm4(a_[mt], sA + off);
            }
            #pragma unroll
            for (int p = 0; p < 4; p++) {
                int row = wn * 64 + p * 16 + (lane & 7) + ((lane >> 4) & 1) * 8;
                uint32_t off = (uint32_t)row * 144 + ks * 32 + (((lane >> 3) & 1) << 4);
                ldm4(b_[p], sB + off);
            }
            #pragma unroll
            for (int mt = 0; mt < 2; mt++)
                #pragma unroll
                for (int nt = 0; nt < 8; nt++)
                    mma16816(acc[mt][nt], a_[mt], &b_[nt >> 1][(nt & 1) * 2]);
        }
        __syncthreads();
    }

    // epilogue
    #pragma unroll
    for (int mt = 0; mt < 2; mt++) {
        #pragma unroll
        for (int half = 0; half < 2; half++) {
            int row = m0 + wm * 32 + mt * 16 + (lane >> 2) + half * 8;
            if (row >= M) continue;
            #pragma unroll
            for (int nt = 0; nt < 8; nt++) {
                int col = n0 + wn * 64 + nt * 8 + (lane & 3) * 2;
                float vx = acc[mt][nt][half * 2 + 0];
                float vy = acc[mt][nt][half * 2 + 1];
                size_t go = (size_t)row * 1024 + col;
                if (Cf) {
                    if (bias) { vx += bias[col]; vy += bias[col + 1]; }
                    float2 v2; v2.x = vx; v2.y = vy;
                    if (resid) {
                        float2 rv = *reinterpret_cast<const float2*>(resid + go);
                        v2.x += rv.x; v2.y += rv.y;
                    }
                    *reinterpret_cast<float2*>(Cf + go) = v2;
                } else {
                    *reinterpret_cast<ushort2*>(Ob + go) = make_ushort2(
                        h2u(__float2half_rn(vx * scale)),
                        h2u(__float2half_rn(vy * scale)));
                }
            }
        }
    }
}

// =======================================================================
// segment fix-up: rows l in [1027,1030) use weight set 1 (exact fp32 ->
// fp16 out; q scaled by 0.125)
// =======================================================================
__global__ void __launch_bounds__(256) seg_fix(const float* __restrict__ wq1,
                                               const float* __restrict__ wk1,
                                               const float* __restrict__ wv1)
{
    int which = blockIdx.y;
    const float* W = (which == 0) ? wq1 : (which == 1) ? wk1 : wv1;
    hf* Ob = (which == 0) ? g_qb : (which == 1) ? g_kb : g_vb;
    float scale = (which == 0) ? 0.125f : 1.0f;
    int batch = blockIdx.x / 3, s = blockIdx.x % 3;
    int row = batch * L_ + (L_ - 3) + s;

    __shared__ float xs[1024];
    for (int i = threadIdx.x; i < 1024; i += 256) xs[i] = g_xn[(size_t)row * 1024 + i];
    __syncthreads();

    float a[4] = {0.f, 0.f, 0.f, 0.f};
    const float* Wc = W + threadIdx.x;
    for (int k = 0; k < 1024; k++) {
        float xv = xs[k];
        const float* wr = Wc + (size_t)k * 1024;
        a[0] += xv * wr[0];
        a[1] += xv * wr[256];
        a[2] += xv * wr[512];
        a[3] += xv * wr[768];
    }
    #pragma unroll
    for (int j = 0; j < 4; j++) {
        size_t off = (size_t)row * 1024 + threadIdx.x + j * 256;
        Ob[off] = __float2half_rn(a[j] * scale);
    }
}

// =======================================================================
// tensorized fused attention (single fp16, cp.async double-buffered K/V)
// block = (qt, h, b): 32 query rows, 256 threads (8 warps, 2M x 4N)
// smem: S 32x1032 f32 | Qb 32x72 | KV 2 stages 128x72 | Pb 32x136
// =======================================================================
#define SST 1032
#define OFF_Q  132096
#define OFF_KV (OFF_Q + 32*72*2)            // 136704
#define KVSTG  18432
#define OFF_P  (OFF_KV + 2*KVSTG)           // 173568
#define ATTN_SMEM (OFF_P + 32*136*2)        // 182272
#define NTILE 9

__global__ void __launch_bounds__(256) attn_mma(float* __restrict__ attn_out)
{
    extern __shared__ char sm[];
    float* S = reinterpret_cast<float*>(sm);
    hf* Qb = reinterpret_cast<hf*>(sm + OFF_Q);
    hf* Pb = reinterpret_cast<hf*>(sm + OFF_P);
    const uint32_t uQ = smem_u32(Qb);
    const uint32_t uKV = smem_u32(sm + OFF_KV);
    const uint32_t uP = smem_u32(Pb);

    const int tid = threadIdx.x;
    const int wid = tid >> 5, lane = tid & 31;
    const int wm = wid & 1, wn = wid >> 1;      // 2 (M) x 4 (N)
    const int qt = blockIdx.x, h = blockIdx.y, b = blockIdx.z;
    const int q0 = qt * 32;
    const size_t headq = (size_t)b * L_ * 1024 + h * 64;

    // ---- cp.async tile prefetch (128 rows x 64 fp16) ----
    auto prefetch_t = [&](const hf* src, int kt, int stg) {
        uint32_t base = uKV + stg * KVSTG;
        #pragma unroll
        for (int t = 0; t < 4; t++) {
            int idx = tid + t * 256;          // 0..1023
            int r = idx >> 3;
            int cb = (idx & 7) * 16;
            int l = kt + r;
            int sz = (l < L_) ? 16 : 0;
            int lr = (l < L_) ? l : 0;
            cpa(base + (uint32_t)r * 144 + cb,
                (const char*)(src + headq + (size_t)lr * 1024) + cb, sz);
        }
        cpa_commit();
    };

    prefetch_t(g_kb, 0, 0);

    // ---- load Q (pre-scaled fp16) ----
    #pragma unroll
    for (int t = 0; t < 2; t++) {
        int idx = tid + t * 256;
        int r = idx >> 4, c4 = (idx & 15) * 4;
        int l = q0 + r;
        ushort4 v = make_ushort4(0, 0, 0, 0);
        if (l < L_)
            v = *reinterpret_cast<const ushort4*>(g_qb + headq + (size_t)l * 1024 + c4);
        *reinterpret_cast<ushort4*>(Qb + r * 72 + c4) = v;
    }

    // ---- phase 1: S = Q.K^T ----
    for (int t9 = 0; t9 < NTILE; t9++) {
        if (t9 + 1 < NTILE) {
            prefetch_t(g_kb, (t9 + 1) * 128, (t9 + 1) & 1);
            asm volatile("cp.async.wait_group 1;");
        } else {
            asm volatile("cp.async.wait_group 0;");
        }
        __syncthreads();
        uint32_t uK = uKV + (t9 & 1) * KVSTG;
        int kt = t9 * 128;

        float acc[4][4];
        #pragma unroll
        for (int i = 0; i < 4; i++)
            #pragma unroll
            for (int c = 0; c < 4; c++) acc[i][c] = 0.f;

        #pragma unroll
        for (int ks = 0; ks < 4; ks++) {
            uint32_t q_[4], k_[2][4];
            {
                int row = wm * 16 + (lane & 15);
                uint32_t off = (uint32_t)row * 144 + ks * 32 + ((lane >> 4) << 4);
                ldm4(q_, uQ + off);
            }
            #pragma unroll
            for (int p = 0; p < 2; p++) {
                int row = wn * 32 + p * 16 + (lane & 7) + ((lane >> 4) & 1) * 8;
                uint32_t off = (uint32_t)row * 144 + ks * 32 + (((lane >> 3) & 1) << 4);
                ldm4(k_[p], uK + off);
            }
            #pragma unroll
            for (int nt = 0; nt < 4; nt++)
                mma16816(acc[nt], q_, &k_[nt >> 1][(nt & 1) * 2]);
        }

        int r0 = wm * 16 + (lane >> 2);
        #pragma unroll
        for (int nt = 0; nt < 4; nt++) {
            int col = kt + wn * 32 + nt * 8 + (lane & 3) * 2;
            if (col < L_)     S[r0 * SST + col]           = acc[nt][0];
            if (col + 1 < L_) S[r0 * SST + col + 1]       = acc[nt][1];
            if (col < L_)     S[(r0 + 8) * SST + col]     = acc[nt][2];
            if (col + 1 < L_) S[(r0 + 8) * SST + col + 1] = acc[nt][3];
        }
        __syncthreads();
    }

    // overlap: start V tile 0 load during softmax
    prefetch_t(g_vb, 0, 0);

    // ---- softmax + attn write (warp per 4 rows) ----
    for (int r = wid * 4; r < wid * 4 + 4; r++) {
        int l = q0 + r;
        if (l >= L_) continue;
        float* Sr = S + r * SST;
        float m = -1e30f;
        for (int j = lane; j < L_; j += 32) m = fmaxf(m, Sr[j]);
        #pragma unroll
        for (int o = 16; o; o >>= 1) m = fmaxf(m, __shfl_xor_sync(0xffffffffu, m, o));
        float ssum = 0.f;
        for (int j = lane; j < L_; j += 32) { float e = __expf(Sr[j] - m); Sr[j] = e; ssum += e; }
        #pragma unroll
        for (int o = 16; o; o >>= 1) ssum += __shfl_xor_sync(0xffffffffu, ssum, o);
        float inv = 1.f / ssum;
        size_t abase = ((size_t)(b * H_ + h) * L_ + l) * L_;
        for (int j = lane; j < L_; j += 32) {
            float p = Sr[j] * inv;
            Sr[j] = p;
            if (attn_out) attn_out[abase + j] = p;
        }
    }
    __syncthreads();

    // ---- phase 2: O = P.V ----
    float acc2[2][4];
    #pragma unroll
    for (int i = 0; i < 2; i++)
        #pragma unroll
        for (int c = 0; c < 4; c++) acc2[i][c] = 0.f;

    for (int t9 = 0; t9 < NTILE; t9++) {
        if (t9 + 1 < NTILE) prefetch_t(g_vb, (t9 + 1) * 128, (t9 + 1) & 1);
        int kt = t9 * 128;
        // convert P tile -> fp16 (overlaps the V load)
        #pragma unroll
        for (int t = 0; t < 16; t++) {
            int idx = tid + t * 256;          // 0..4095
            int r = idx >> 7, c = idx & 127;
            int col = kt + c;
            float p = (col < L_) ? S[r * SST + col] : 0.f;
            Pb[r * 136 + c] = __float2half_rn(p);
        }
        if (t9 + 1 < NTILE) asm volatile("cp.async.wait_group 1;");
        else                asm volatile("cp.async.wait_group 0;");
        __syncthreads();
        uint32_t uV = uKV + (t9 & 1) * KVSTG;

        #pragma unroll
        for (int ks = 0; ks < 8; ks++) {
            uint32_t p_[4], v_[4];
            {
                int row = wm * 16 + (lane & 15);
                uint32_t off = (uint32_t)row * 272 + ks * 32 + ((lane >> 4) << 4);
                ldm4(p_, uP + off);
            }
            {
                int row = ks * 16 + (lane & 15);
                uint32_t off = (uint32_t)row * 144 + wn * 32 + ((lane >> 4) << 4);
                ldm4t(v_, uV + off);
            }
            #pragma unroll
            for (int nt = 0; nt < 2; nt++)
                mma16816(acc2[nt], p_, &v_[nt * 2]);
        }
        __syncthreads();
    }

    // output -> fp16 (FC GEMM input)
    #pragma unroll
    for (int half = 0; half < 2; half++) {
        int r = wm * 16 + (lane >> 2) + half * 8;
        int l = q0 + r;
        if (l >= L_) continue;
        #pragma unroll
        for (int nt = 0; nt < 2; nt++) {
            int d = wn * 16 + nt * 8 + (lane & 3) * 2;
            size_t go = headq + (size_t)l * 1024 + d;
            *reinterpret_cast<ushort2*>(g_aob + go) = make_ushort2(
                h2u(__float2half_rn(acc2[nt][half * 2 + 0])),
                h2u(__float2half_rn(acc2[nt][half * 2 + 1])));
        }
    }
}

// =======================================================================
// launch
// =======================================================================
extern "C" void kernel_launch(void* const* d_in, const int* in_sizes, int n_in,
                              void* d_out, int out_size)
{
    const float* x    = (const float*)d_in[0];
    const float* wq0  = (const float*)d_in[1];
    const float* wq1  = (const float*)d_in[2];
    const float* wk0  = (const float*)d_in[3];
    const float* wk1  = (const float*)d_in[4];
    const float* wv0  = (const float*)d_in[5];
    const float* wv1  = (const float*)d_in[6];
    const float* fc_w = (const float*)d_in[7];
    const float* fc_b = (const float*)d_in[8];
    const float* ln_g = (const float*)d_in[9];
    const float* ln_b = (const float*)d_in[10];
    float* out = (float*)d_out;

    hf *p_xb, *p_qb, *p_kb, *p_vb, *p_aob, *p_wt;
    cudaGetSymbolAddress((void**)&p_xb,  g_xb);
    cudaGetSymbolAddress((void**)&p_qb,  g_qb);
    cudaGetSymbolAddress((void**)&p_kb,  g_kb);
    cudaGetSymbolAddress((void**)&p_vb,  g_vb);
    cudaGetSymbolAddress((void**)&p_aob, g_aob);
    cudaGetSymbolAddress((void**)&p_wt,  g_wt);

    float* attn_ptr = ((size_t)out_size >= OUT_ELEMS + ATTN_ELEMS)
                        ? (out + OUT_ELEMS) : nullptr;

    cudaFuncSetAttribute(mma_gemm, cudaFuncAttributeMaxDynamicSharedMemorySize, 2 * GSTG);
    cudaFuncSetAttribute(attn_mma, cudaFuncAttributeMaxDynamicSharedMemorySize, ATTN_SMEM);

    // 1) LayerNorm (f32 + fp16)
    ln_kernel<<<M_, 256>>>(x, ln_g, ln_b);

    // 2) transpose+convert the 4 main weights
    dim3 tg(32, 32);
    tconv_kernel<<<tg, 256>>>(wq0,  p_wt + 0 * (size_t)WSZ);
    tconv_kernel<<<tg, 256>>>(wk0,  p_wt + 1 * (size_t)WSZ);
    tconv_kernel<<<tg, 256>>>(wv0,  p_wt + 2 * (size_t)WSZ);
    tconv_kernel<<<tg, 256>>>(fc_w, p_wt + 3 * (size_t)WSZ);

    // 3) fused QKV projections (fp16 epilogue, Q pre-scaled)
    dim3 gq(8, (M_ + 127) / 128, 3);
    mma_gemm<<<gq, 256, 2 * GSTG>>>(p_xb, p_wt, nullptr, nullptr, nullptr,
                                    p_qb, p_kb, p_vb, M_);

    // 4) exact fp32 fix for the 24 weight-set-1 rows
    seg_fix<<<dim3(24, 3), 256>>>(wq1, wk1, wv1);

    // 5) tensorized attention (writes attn + fp16 ao)
    attn_mma<<<dim3((L_ + 31) / 32, H_, B_), 256, ATTN_SMEM>>>(attn_ptr);

    // 6) FC (+bias+residual) -> out
    dim3 gf(8, (M_ + 127) / 128, 1);
    mma_gemm<<<gf, 256, 2 * GSTG>>>(p_aob, p_wt + 3 * (size_t)WSZ,
                                    out, fc_b, x,
                                    nullptr, nullptr, nullptr, M_);
}